// round 11
// baseline (speedup 1.0000x reference)
#include <cuda_runtime.h>
#include <cuda_bf16.h>
#include <cstdint>
#include <cstddef>

#define T_    256
#define B_    64
#define DIN_  512
#define H_    1024
#define CH_   2048
#define G_    6144
#define DOUT_ 512
#define MB_   (T_*B_)
#define KSPLIT 3
#define NCTA_STEP 144
#define HB_   ((size_t)B_ * CH_)

typedef __nv_bfloat16 bf16;

// ---------------- scratch (device globals) ----------------------------------
__device__ float g_gx[(size_t)MB_ * G_];
__device__ float g_ghp[(size_t)KSPLIT * B_ * G_];
__device__ bf16 g_xh[(size_t)MB_ * DIN_],  g_xl[(size_t)MB_ * DIN_];
__device__ bf16 g_xeh[(size_t)MB_ * H_],   g_xel[(size_t)MB_ * H_];
__device__ bf16 g_weh[(size_t)H_ * DIN_],  g_wel[(size_t)H_ * DIN_];
__device__ bf16 g_wihh[(size_t)G_ * H_],   g_wihl[(size_t)G_ * H_];
__device__ bf16 g_whh_hi[(size_t)G_ * CH_], g_whh_lo[(size_t)G_ * CH_];
__device__ bf16 g_wmuh[(size_t)DOUT_ * H_], g_wmul[(size_t)DOUT_ * H_];
__device__ bf16 g_wsgh[(size_t)DOUT_ * H_], g_wsgl[(size_t)DOUT_ * H_];
__device__ bf16 g_hhA[(size_t)MB_ * CH_],  g_hlA[(size_t)MB_ * CH_];
__device__ bf16 g_hh0[HB_],                g_hl0[HB_];
__device__ unsigned int g_cnt[2 * T_];

__device__ __forceinline__ float act_elu(float v) {
    return v > 0.0f ? v : expm1f(v);
}
__device__ __forceinline__ float act_softplus01(float v) {
    return fmaxf(v, 0.0f) + log1pf(expf(-fabsf(v))) + 0.1f;
}

// ---------------- sm_80-era primitives ---------------------------------------
__device__ __forceinline__ uint32_t smem_u32(const void* p) {
    uint32_t a;
    asm("{ .reg .u64 t; cvta.to.shared.u64 t, %1; cvt.u32.u64 %0, t; }"
        : "=r"(a) : "l"(p));
    return a;
}
__device__ __forceinline__ void cp16(uint32_t dst, const void* src) {
    asm volatile("cp.async.cg.shared.global [%0], [%1], 16;"
                 :: "r"(dst), "l"(src) : "memory");
}
__device__ __forceinline__ void ldm4(uint32_t addr, uint32_t r[4]) {
    asm volatile("ldmatrix.sync.aligned.m8n8.x4.shared.b16 {%0,%1,%2,%3}, [%4];"
                 : "=r"(r[0]), "=r"(r[1]), "=r"(r[2]), "=r"(r[3]) : "r"(addr));
}
__device__ __forceinline__ void mma16816(float d[4], const uint32_t a[4],
                                         uint32_t b0, uint32_t b1) {
    asm volatile(
        "mma.sync.aligned.m16n8k16.row.col.f32.bf16.bf16.f32 "
        "{%0,%1,%2,%3}, {%4,%5,%6,%7}, {%8,%9}, {%0,%1,%2,%3};"
        : "+f"(d[0]), "+f"(d[1]), "+f"(d[2]), "+f"(d[3])
        : "r"(a[0]), "r"(a[1]), "r"(a[2]), "r"(a[3]), "r"(b0), "r"(b1));
}
#define CPW(n) asm volatile("cp.async.wait_group " #n ";" ::: "memory")
#define CPC()  asm volatile("cp.async.commit_group;" ::: "memory")

// =============================================================================
__global__ void init_kernel() {
    int idx = blockIdx.x * 256 + threadIdx.x;          // grid 512 -> 131072
    g_hh0[idx] = __float2bfloat16(0.0f);
    g_hl0[idx] = __float2bfloat16(0.0f);
    if (idx < 2 * T_) g_cnt[idx] = 0u;
}

__global__ void pad_kernel() {}   // launch-count pad so ncu -s 5 hits step_persist

// one kernel splitting all six fp32 tensors -> bf16 hi/lo (1024 floats/block)
__global__ void split_all(const float* __restrict__ x,
                          const float* __restrict__ We,
                          const float* __restrict__ Wih,
                          const float* __restrict__ Whh,
                          const float* __restrict__ Wmu,
                          const float* __restrict__ Wsig) {
    int b = blockIdx.x;
    const float* src; bf16 *hi, *lo; int base;
    if      (b < 8192)  { src = x;    hi = g_xh;     lo = g_xl;     base = b; }
    else if (b < 8704)  { src = We;   hi = g_weh;    lo = g_wel;    base = b - 8192; }
    else if (b < 14848) { src = Wih;  hi = g_wihh;   lo = g_wihl;   base = b - 8704; }
    else if (b < 27136) { src = Whh;  hi = g_whh_hi; lo = g_whh_lo; base = b - 14848; }
    else if (b < 27648) { src = Wmu;  hi = g_wmuh;   lo = g_wmul;   base = b - 27136; }
    else                { src = Wsig; hi = g_wsgh;   lo = g_wsgl;   base = b - 27648; }
    size_t i = ((size_t)base * 256 + threadIdx.x) * 4;
    float4 w = *(const float4*)(src + i);
    float f[4] = {w.x, w.y, w.z, w.w};
#pragma unroll
    for (int k = 0; k < 4; k++) {
        bf16 h = __float2bfloat16(f[k]);
        hi[i + k] = h;
        lo[i + k] = __float2bfloat16(f[k] - __bfloat162float(h));
    }
}

// =============================================================================
// gemm_tc (proven): C = act(A @ W^T + bias) via bf16 HMMA 3-term split.
// =============================================================================
#define GT_TILE  10240        // 128 rows x 80 B
#define GT_STAGE (4*GT_TILE)
#define GT_SMEM  (2*GT_STAGE)

template <int ACT, int SPLIT>
__global__ __launch_bounds__(256) void gemm_tc(
    const bf16* __restrict__ Ah, const bf16* __restrict__ Al, int lda,
    const bf16* __restrict__ Wh, const bf16* __restrict__ Wl, int ldw,
    const float* __restrict__ bias,
    float* __restrict__ C, int ldc,
    bf16* __restrict__ Ch, bf16* __restrict__ Cl,
    int K)
{
    extern __shared__ __align__(16) char smem[];
    const uint32_t sb = smem_u32(smem);
    const int tid = threadIdx.x;
    const int w = tid >> 5, l = tid & 31;
    const int wm = w >> 1, wn = w & 1;
    const long m0 = (long)blockIdx.y * 128;
    const long n0 = (long)blockIdx.x * 128;

    auto load_stage = [&](int slot, int kt) {
        const uint32_t dst = sb + slot * GT_STAGE;
        const int k0 = kt * 32;
#pragma unroll
        for (int i = 0; i < 2; i++) {
            int o = i * 256 + tid;
            int row = o >> 2, c = o & 3;
            size_t ao = (m0 + row) * (size_t)lda + k0 + c * 8;
            size_t wo = (n0 + row) * (size_t)ldw + k0 + c * 8;
            uint32_t d = dst + row * 80 + c * 16;
            cp16(d,               Ah + ao);
            cp16(d + GT_TILE,     Al + ao);
            cp16(d + 2*GT_TILE,   Wh + wo);
            cp16(d + 3*GT_TILE,   Wl + wo);
        }
        CPC();
    };

    const int nst = K >> 5;
    load_stage(0, 0);
    load_stage(1, 1);

    const uint32_t aoff = (uint32_t)((l & 15) * 80 + (l >> 4) * 16);
    const uint32_t woff = (uint32_t)(((l & 7) + ((l >> 4) & 1) * 8) * 80
                                     + ((l >> 3) & 1) * 16);

    float acc[2][8][4];
#pragma unroll
    for (int a = 0; a < 2; a++)
#pragma unroll
        for (int b = 0; b < 8; b++)
#pragma unroll
            for (int c = 0; c < 4; c++) acc[a][b][c] = 0.0f;

    for (int s = 0; s < nst; s++) {
        const int slot = s & 1;
        if (s + 1 < nst) CPW(1);
        else             CPW(0);
        __syncthreads();

        const uint32_t stg = sb + slot * GT_STAGE;
        const uint32_t aH = stg + wm * 2560 + aoff;
        const uint32_t wH = stg + 2*GT_TILE + wn * 5120 + woff;

#pragma unroll
        for (int k16 = 0; k16 < 2; k16++) {
            uint32_t ah[2][4], al[2][4], wh[4][4], wl[4][4];
#pragma unroll
            for (int mf = 0; mf < 2; mf++) {
                ldm4(aH + mf * 1280 + k16 * 32, ah[mf]);
                ldm4(aH + GT_TILE + mf * 1280 + k16 * 32, al[mf]);
            }
#pragma unroll
            for (int g = 0; g < 4; g++) {
                ldm4(wH + g * 1280 + k16 * 32, wh[g]);
                ldm4(wH + GT_TILE + g * 1280 + k16 * 32, wl[g]);
            }
#pragma unroll
            for (int mf = 0; mf < 2; mf++)
#pragma unroll
                for (int nf = 0; nf < 8; nf++) {
                    const uint32_t* bp = wh[nf >> 1];
                    const uint32_t* lp = wl[nf >> 1];
                    uint32_t b0 = bp[(nf & 1) * 2], b1 = bp[(nf & 1) * 2 + 1];
                    uint32_t c0 = lp[(nf & 1) * 2], c1 = lp[(nf & 1) * 2 + 1];
                    mma16816(acc[mf][nf], ah[mf], b0, b1);
                    mma16816(acc[mf][nf], ah[mf], c0, c1);
                    mma16816(acc[mf][nf], al[mf], b0, b1);
                }
        }
        __syncthreads();
        if (s + 2 < nst) load_stage(slot, s + 2);
    }

    const int r0 = wm * 32 + (l >> 2);
    const int c0 = wn * 64 + (l & 3) * 2;
#pragma unroll
    for (int mf = 0; mf < 2; mf++)
#pragma unroll
        for (int nf = 0; nf < 8; nf++) {
            const long col = n0 + c0 + nf * 8;
            const float b0 = bias[col], b1 = bias[col + 1];
#pragma unroll
            for (int rr = 0; rr < 2; rr++) {
                const long row = m0 + r0 + mf * 16 + rr * 8;
                float v0 = acc[mf][nf][rr * 2]     + b0;
                float v1 = acc[mf][nf][rr * 2 + 1] + b1;
                if (ACT == 1) { v0 = act_elu(v0); v1 = act_elu(v1); }
                else if (ACT == 2) { v0 = act_softplus01(v0); v1 = act_softplus01(v1); }
                if (SPLIT) {
                    bf16 h0 = __float2bfloat16(v0);
                    bf16 h1 = __float2bfloat16(v1);
                    *(__nv_bfloat162*)&Ch[row * (long)ldc + col] =
                        __nv_bfloat162(h0, h1);
                    *(__nv_bfloat162*)&Cl[row * (long)ldc + col] = __nv_bfloat162(
                        __float2bfloat16(v0 - __bfloat162float(h0)),
                        __float2bfloat16(v1 - __bfloat162float(h1)));
                } else {
                    *(float2*)&C[row * (long)ldc + col] = make_float2(v0, v1);
                }
            }
        }
}

// =============================================================================
// step_persist v3: 512 threads (16 warps) for latency hiding.
// grid (48 gate-j blocks, 3 k-splits) = 144 CTAs. Warp w: wm=w>>1 -> 16-row
// j sub-tile, wn=w&1 -> 32-b half. Stage slot layout unchanged.
// =============================================================================
#define ST_ALO  10240
#define ST_BHI  20480
#define ST_BLO  25600
#define ST_SZ   30720
#define SM_P    (4 * ST_SZ)      // 122880

__global__ __launch_bounds__(512, 1) void step_persist(
    const bf16* __restrict__ whh_hi,
    const bf16* __restrict__ whh_lo,
    const bf16* __restrict__ hh0,
    const bf16* __restrict__ hl0,
    const float* __restrict__ gx,       // [T][64][6144]
    const float* __restrict__ bhh,
    float* __restrict__ ghp,            // [KSPLIT][64][6144]
    float* __restrict__ hidden,         // [T][64][2048]
    bf16* __restrict__ hhA,
    bf16* __restrict__ hlA,
    unsigned int* __restrict__ cnt)     // [2*T]
{
    extern __shared__ __align__(16) char smem[];
    const uint32_t sb = smem_u32(smem);
    const int tid = threadIdx.x;
    const int w = tid >> 5, l = tid & 31;
    const int jg0 = blockIdx.x * 128;
    const int ks = blockIdx.y;
    const int kbeg = ks * 672;
    const int nst  = (ks == 2) ? 22 : 21;       // 672,672,704
    const int wm = w >> 1, wn = w & 1;
    const int cta = blockIdx.y * 48 + blockIdx.x;

    auto loadA = [&](int s) {
        const uint32_t dst = sb + (s & 3) * ST_SZ;
        const int k0 = kbeg + s * 32;
        int row = tid >> 2, c = tid & 3;          // 512 copies = 128 rows x 4
        size_t off = (size_t)(jg0 + row) * CH_ + k0 + c * 8;
        cp16(dst + row * 80 + c * 16,          whh_hi + off);
        cp16(dst + ST_ALO + row * 80 + c * 16, whh_lo + off);
    };
    auto loadB = [&](int s, const bf16* hh_in, const bf16* hl_in) {
        if (tid < 256) {
            const uint32_t dst = sb + (s & 3) * ST_SZ;
            const int k0 = kbeg + s * 32;
            int row = tid >> 2, c = tid & 3;      // 256 copies = 64 rows x 4
            size_t off = (size_t)row * CH_ + k0 + c * 8;
            cp16(dst + ST_BHI + row * 80 + c * 16, hh_in + off);
            cp16(dst + ST_BLO + row * 80 + c * 16, hl_in + off);
        }
    };

#pragma unroll
    for (int i = 0; i < 4; i++) { loadA(i); CPC(); }
#pragma unroll
    for (int i = 0; i < 4; i++) { loadB(i, hh0, hl0); CPC(); }

    const uint32_t aoff = (uint32_t)((l & 15) * 80 + (l >> 4) * 16);
    const uint32_t boff = (uint32_t)(((wn * 32) + (l & 7) + ((l >> 4) & 1) * 8) * 80
                                     + ((l >> 3) & 1) * 16);

    // phase-2 per-thread constants (first 64 CTAs x 512 threads cover B_*CH_/4)
    const int idx4 = cta * 512 + tid;
    const bool p2 = (idx4 < B_ * CH_ / 4);
    const int pb  = idx4 >> 9;
    const int pj4 = idx4 & 511;
    float4 br4 = make_float4(0,0,0,0), bz4 = br4, bn4 = br4;
    if (p2) {
        br4 = *(const float4*)(bhh + pj4 * 4);
        bz4 = *(const float4*)(bhh + CH_ + pj4 * 4);
        bn4 = *(const float4*)(bhh + 2 * CH_ + pj4 * 4);
    }
    float4 hp = make_float4(0.f, 0.f, 0.f, 0.f);

    float acc[4][4];
#pragma unroll
    for (int b = 0; b < 4; b++)
#pragma unroll
        for (int c = 0; c < 4; c++) acc[b][c] = 0.0f;

    for (int t = 0; t < T_; t++) {
        const bf16* hh_cur = (t == 0) ? hh0 : hhA + (size_t)(t - 1) * HB_;
        const bf16* hl_cur = (t == 0) ? hl0 : hlA + (size_t)(t - 1) * HB_;

        // ---------------- phase 1 ----------------
        for (int s = 0; s < nst; s++) {
            {
                int pend = nst - 1 - s;
                if (pend >= 3)      CPW(3);
                else if (pend == 2) CPW(2);
                else if (pend == 1) CPW(1);
                else                CPW(0);
            }
            __syncthreads();

            const uint32_t stg = sb + (s & 3) * ST_SZ;
            const uint32_t aHb = stg + (uint32_t)(wm * 1280) + aoff;
            const uint32_t bHb = stg + ST_BHI + boff;
            const uint32_t bLb = stg + ST_BLO + boff;

            uint32_t ah[2][4], al[2][4], bh[2][2][4], bl[2][2][4];
#pragma unroll
            for (int k16 = 0; k16 < 2; k16++) {
                ldm4(aHb + k16 * 32, ah[k16]);
                ldm4(aHb + ST_ALO + k16 * 32, al[k16]);
#pragma unroll
                for (int nf = 0; nf < 2; nf++) {
                    ldm4(bHb + nf * 1280 + k16 * 32, bh[k16][nf]);
                    ldm4(bLb + nf * 1280 + k16 * 32, bl[k16][nf]);
                }
            }
            __syncthreads();
            if (s + 4 < nst) { loadA(s + 4); loadB(s + 4, hh_cur, hl_cur); CPC(); }

#pragma unroll
            for (int k16 = 0; k16 < 2; k16++)
#pragma unroll
                for (int nf = 0; nf < 4; nf++) {
                    const uint32_t* bp = bh[k16][nf >> 1];
                    const uint32_t* lp = bl[k16][nf >> 1];
                    uint32_t b0 = bp[(nf & 1) * 2], b1 = bp[(nf & 1) * 2 + 1];
                    uint32_t c0 = lp[(nf & 1) * 2], c1 = lp[(nf & 1) * 2 + 1];
                    mma16816(acc[nf], ah[k16], b0, b1);
                    mma16816(acc[nf], ah[k16], c0, c1);
                    mma16816(acc[nf], al[k16], b0, b1);
                }
        }

        // write partials + reset
        {
            float* base = ghp + (size_t)ks * B_ * G_;
            const int j = jg0 + wm * 16 + (l >> 2);
            const int bb = wn * 32 + (l & 3) * 2;
#pragma unroll
            for (int nf = 0; nf < 4; nf++) {
                const int b = bb + nf * 8;
                base[(size_t)b * G_ + j]           = acc[nf][0];
                base[(size_t)(b + 1) * G_ + j]     = acc[nf][1];
                base[(size_t)b * G_ + j + 8]       = acc[nf][2];
                base[(size_t)(b + 1) * G_ + j + 8] = acc[nf][3];
                acc[nf][0] = acc[nf][1] = acc[nf][2] = acc[nf][3] = 0.0f;
            }
        }

        // ---- barrier 1; prefetch next-step A during spin ----
        __threadfence();
        __syncthreads();
        if (t + 1 < T_) {
#pragma unroll
            for (int i = 0; i < 4; i++) { loadA(i); CPC(); }
        }
        if (tid == 0) {
            unsigned v = atomicAdd(&cnt[2 * t], 1u) + 1;
            if (v < (unsigned)NCTA_STEP) {
                volatile unsigned* p = &cnt[2 * t];
                while (*p < (unsigned)NCTA_STEP) { }
            }
        }
        __syncthreads();

        // ---------------- phase 2 ----------------
        if (p2) {
            const float* gx_t = gx + (size_t)t * B_ * G_;
            const long go = (long)pb * G_ + pj4 * 4;

            float4 xr = *(const float4*)(gx_t + go);
            float4 xz = *(const float4*)(gx_t + go + CH_);
            float4 xn = *(const float4*)(gx_t + go + 2*CH_);

            float4 hr = *(const float4*)(ghp + go);
            float4 hz = *(const float4*)(ghp + go + CH_);
            float4 hn = *(const float4*)(ghp + go + 2*CH_);
#pragma unroll
            for (int s = 1; s < KSPLIT; s++) {
                const float* p = ghp + (size_t)s * B_ * G_ + go;
                float4 a = *(const float4*)(p);
                float4 c = *(const float4*)(p + CH_);
                float4 d = *(const float4*)(p + 2*CH_);
                hr.x += a.x; hr.y += a.y; hr.z += a.z; hr.w += a.w;
                hz.x += c.x; hz.y += c.y; hz.z += c.z; hz.w += c.w;
                hn.x += d.x; hn.y += d.y; hn.z += d.z; hn.w += d.w;
            }
            float xrv[4] = {xr.x, xr.y, xr.z, xr.w};
            float xzv[4] = {xz.x, xz.y, xz.z, xz.w};
            float xnv[4] = {xn.x, xn.y, xn.z, xn.w};
            float hrv[4] = {hr.x + br4.x, hr.y + br4.y, hr.z + br4.z, hr.w + br4.w};
            float hzv[4] = {hz.x + bz4.x, hz.y + bz4.y, hz.z + bz4.z, hz.w + bz4.w};
            float hnv[4] = {hn.x + bn4.x, hn.y + bn4.y, hn.z + bn4.z, hn.w + bn4.w};
            float hpv[4] = {hp.x, hp.y, hp.z, hp.w};
            float ov[4];
#pragma unroll
            for (int i = 0; i < 4; i++) {
                float r = 1.0f / (1.0f + expf(-(xrv[i] + hrv[i])));
                float z = 1.0f / (1.0f + expf(-(xzv[i] + hzv[i])));
                float n = tanhf(xnv[i] + r * hnv[i]);
                ov[i] = (1.0f - z) * n + z * hpv[i];
            }
            hp = make_float4(ov[0], ov[1], ov[2], ov[3]);

            const long ho = (long)pb * CH_ + pj4 * 4;
            *(float4*)(hidden + (size_t)t * HB_ + ho) = hp;
            bf16* hhp = hhA + (size_t)t * HB_ + ho;
            bf16* hlp = hlA + (size_t)t * HB_ + ho;
#pragma unroll
            for (int i = 0; i < 4; i++) {
                bf16 hi = __float2bfloat16(ov[i]);
                hhp[i] = hi;
                hlp[i] = __float2bfloat16(ov[i] - __bfloat162float(hi));
            }
        }

        // ---- barrier 2 ----
        __threadfence();
        __syncthreads();
        if (tid == 0) {
            unsigned v = atomicAdd(&cnt[2 * t + 1], 1u) + 1;
            if (v < (unsigned)NCTA_STEP) {
                volatile unsigned* p = &cnt[2 * t + 1];
                while (*p < (unsigned)NCTA_STEP) { }
            }
        }
        __syncthreads();

        if (t + 1 < T_) {
            const bf16* nh = hhA + (size_t)t * HB_;
            const bf16* nl = hlA + (size_t)t * HB_;
#pragma unroll
            for (int i = 0; i < 4; i++) { loadB(i, nh, nl); CPC(); }
        }
    }
}

// =============================================================================
extern "C" void kernel_launch(void* const* d_in, const int* in_sizes, int n_in,
                              void* d_out, int out_size)
{
    const float* x    = (const float*)d_in[0];
    const float* We   = (const float*)d_in[1];
    const float* be   = (const float*)d_in[2];
    const float* Wih  = (const float*)d_in[3];
    const float* bih  = (const float*)d_in[4];
    const float* Whh  = (const float*)d_in[5];
    const float* bhh  = (const float*)d_in[6];
    const float* Wmu  = (const float*)d_in[7];
    const float* bmu  = (const float*)d_in[8];
    const float* Wsig = (const float*)d_in[9];
    const float* bsig = (const float*)d_in[10];

    float* out        = (float*)d_out;
    float* out_mu     = out;
    float* out_sig    = out + (size_t)MB_ * DOUT_;
    float* out_hidden = out + (size_t)2 * MB_ * DOUT_;

    float *p_gx, *p_ghp;
    bf16 *p_xh, *p_xl, *p_xeh, *p_xel, *p_weh, *p_wel, *p_wihh, *p_wihl;
    bf16 *p_whhh, *p_whhl, *p_wmuh, *p_wmul, *p_wsgh, *p_wsgl;
    bf16 *p_hhA, *p_hlA, *p_hh0, *p_hl0;
    unsigned int* p_cnt;
    cudaGetSymbolAddress((void**)&p_gx, g_gx);
    cudaGetSymbolAddress((void**)&p_ghp, g_ghp);
    cudaGetSymbolAddress((void**)&p_xh, g_xh);
    cudaGetSymbolAddress((void**)&p_xl, g_xl);
    cudaGetSymbolAddress((void**)&p_xeh, g_xeh);
    cudaGetSymbolAddress((void**)&p_xel, g_xel);
    cudaGetSymbolAddress((void**)&p_weh, g_weh);
    cudaGetSymbolAddress((void**)&p_wel, g_wel);
    cudaGetSymbolAddress((void**)&p_wihh, g_wihh);
    cudaGetSymbolAddress((void**)&p_wihl, g_wihl);
    cudaGetSymbolAddress((void**)&p_whhh, g_whh_hi);
    cudaGetSymbolAddress((void**)&p_whhl, g_whh_lo);
    cudaGetSymbolAddress((void**)&p_wmuh, g_wmuh);
    cudaGetSymbolAddress((void**)&p_wmul, g_wmul);
    cudaGetSymbolAddress((void**)&p_wsgh, g_wsgh);
    cudaGetSymbolAddress((void**)&p_wsgl, g_wsgl);
    cudaGetSymbolAddress((void**)&p_hhA, g_hhA);
    cudaGetSymbolAddress((void**)&p_hlA, g_hlA);
    cudaGetSymbolAddress((void**)&p_hh0, g_hh0);
    cudaGetSymbolAddress((void**)&p_hl0, g_hl0);
    cudaGetSymbolAddress((void**)&p_cnt, g_cnt);

    cudaFuncSetAttribute(step_persist, cudaFuncAttributeMaxDynamicSharedMemorySize, SM_P);
    cudaFuncSetAttribute(gemm_tc<0,0>, cudaFuncAttributeMaxDynamicSharedMemorySize, GT_SMEM);
    cudaFuncSetAttribute(gemm_tc<1,0>, cudaFuncAttributeMaxDynamicSharedMemorySize, GT_SMEM);
    cudaFuncSetAttribute(gemm_tc<2,0>, cudaFuncAttributeMaxDynamicSharedMemorySize, GT_SMEM);
    cudaFuncSetAttribute(gemm_tc<1,1>, cudaFuncAttributeMaxDynamicSharedMemorySize, GT_SMEM);

    dim3 blk(256);
    // launch order arranged so ncu (-s 5 -c 1) profiles step_persist (launch #6)
    init_kernel<<<512, blk>>>();                                       // 1
    split_all<<<28160, blk>>>(x, We, Wih, Whh, Wmu, Wsig);             // 2
    gemm_tc<1,1><<<dim3(H_/128, MB_/128), blk, GT_SMEM>>>(             // 3: enc
        p_xh, p_xl, DIN_, p_weh, p_wel, DIN_, be,
        nullptr, H_, p_xeh, p_xel, DIN_);
    gemm_tc<0,0><<<dim3(G_/128, MB_/128), blk, GT_SMEM>>>(             // 4: gx
        p_xeh, p_xel, H_, p_wihh, p_wihl, H_, bih,
        p_gx, G_, nullptr, nullptr, H_);
    pad_kernel<<<1, 32>>>();                                           // 5
    step_persist<<<dim3(48, KSPLIT), 512, SM_P>>>(                     // 6
        p_whhh, p_whhl, p_hh0, p_hl0, p_gx, bhh, p_ghp,
        out_hidden, p_hhA, p_hlA, p_cnt);
    gemm_tc<1,0><<<dim3(DOUT_/128, MB_/128), blk, GT_SMEM>>>(          // 7: mu
        p_hhA, p_hlA, CH_, p_wmuh, p_wmul, H_, bmu,
        out_mu, DOUT_, nullptr, nullptr, H_);
    gemm_tc<2,0><<<dim3(DOUT_/128, MB_/128), blk, GT_SMEM>>>(          // 8: sig
        p_hhA + H_, p_hlA + H_, CH_, p_wsgh, p_wsgl, H_, bsig,
        out_sig, DOUT_, nullptr, nullptr, H_);
}

// round 12
// speedup vs baseline: 1.1318x; 1.1318x over previous
#include <cuda_runtime.h>
#include <cuda_bf16.h>
#include <cstdint>
#include <cstddef>

#define T_    256
#define B_    64
#define DIN_  512
#define H_    1024
#define CH_   2048
#define G_    6144
#define DOUT_ 512
#define MB_   (T_*B_)
#define KSPLIT 3
#define NCTA_STEP 144
#define HB_   ((size_t)B_ * CH_)

typedef __nv_bfloat16 bf16;

// ---------------- scratch (device globals) ----------------------------------
__device__ float g_gx[(size_t)MB_ * G_];
__device__ float g_ghp[(size_t)KSPLIT * B_ * G_];
__device__ bf16 g_xh[(size_t)MB_ * DIN_],  g_xl[(size_t)MB_ * DIN_];
__device__ bf16 g_xeh[(size_t)MB_ * H_],   g_xel[(size_t)MB_ * H_];
__device__ bf16 g_weh[(size_t)H_ * DIN_],  g_wel[(size_t)H_ * DIN_];
__device__ bf16 g_wihh[(size_t)G_ * H_],   g_wihl[(size_t)G_ * H_];
__device__ bf16 g_whh_hi[(size_t)G_ * CH_], g_whh_lo[(size_t)G_ * CH_];
__device__ bf16 g_wmuh[(size_t)DOUT_ * H_], g_wmul[(size_t)DOUT_ * H_];
__device__ bf16 g_wsgh[(size_t)DOUT_ * H_], g_wsgl[(size_t)DOUT_ * H_];
__device__ bf16 g_hhA[(size_t)MB_ * CH_],  g_hlA[(size_t)MB_ * CH_];
__device__ bf16 g_hh0[HB_],                g_hl0[HB_];
__device__ unsigned int g_cnt[2 * T_];

__device__ __forceinline__ float act_elu(float v) {
    return v > 0.0f ? v : expm1f(v);
}
__device__ __forceinline__ float act_softplus01(float v) {
    return fmaxf(v, 0.0f) + log1pf(expf(-fabsf(v))) + 0.1f;
}

// ---------------- sm_80-era primitives ---------------------------------------
__device__ __forceinline__ uint32_t smem_u32(const void* p) {
    uint32_t a;
    asm("{ .reg .u64 t; cvta.to.shared.u64 t, %1; cvt.u32.u64 %0, t; }"
        : "=r"(a) : "l"(p));
    return a;
}
__device__ __forceinline__ void cp16(uint32_t dst, const void* src) {
    asm volatile("cp.async.cg.shared.global [%0], [%1], 16;"
                 :: "r"(dst), "l"(src) : "memory");
}
__device__ __forceinline__ void ldm4(uint32_t addr, uint32_t r[4]) {
    asm volatile("ldmatrix.sync.aligned.m8n8.x4.shared.b16 {%0,%1,%2,%3}, [%4];"
                 : "=r"(r[0]), "=r"(r[1]), "=r"(r[2]), "=r"(r[3]) : "r"(addr));
}
__device__ __forceinline__ void mma16816(float d[4], const uint32_t a[4],
                                         uint32_t b0, uint32_t b1) {
    asm volatile(
        "mma.sync.aligned.m16n8k16.row.col.f32.bf16.bf16.f32 "
        "{%0,%1,%2,%3}, {%4,%5,%6,%7}, {%8,%9}, {%0,%1,%2,%3};"
        : "+f"(d[0]), "+f"(d[1]), "+f"(d[2]), "+f"(d[3])
        : "r"(a[0]), "r"(a[1]), "r"(a[2]), "r"(a[3]), "r"(b0), "r"(b1));
}
#define CPW(n) asm volatile("cp.async.wait_group " #n ";" ::: "memory")
#define CPC()  asm volatile("cp.async.commit_group;" ::: "memory")

// =============================================================================
__global__ void init_kernel() {
    int idx = blockIdx.x * 256 + threadIdx.x;          // grid 512 -> 131072
    g_hh0[idx] = __float2bfloat16(0.0f);
    g_hl0[idx] = __float2bfloat16(0.0f);
    if (idx < 2 * T_) g_cnt[idx] = 0u;
}

__global__ void pad_kernel() {}   // launch-count pad so ncu -s 5 hits step_persist

// one kernel splitting all six fp32 tensors -> bf16 hi/lo (1024 floats/block)
__global__ void split_all(const float* __restrict__ x,
                          const float* __restrict__ We,
                          const float* __restrict__ Wih,
                          const float* __restrict__ Whh,
                          const float* __restrict__ Wmu,
                          const float* __restrict__ Wsig) {
    int b = blockIdx.x;
    const float* src; bf16 *hi, *lo; int base;
    if      (b < 8192)  { src = x;    hi = g_xh;     lo = g_xl;     base = b; }
    else if (b < 8704)  { src = We;   hi = g_weh;    lo = g_wel;    base = b - 8192; }
    else if (b < 14848) { src = Wih;  hi = g_wihh;   lo = g_wihl;   base = b - 8704; }
    else if (b < 27136) { src = Whh;  hi = g_whh_hi; lo = g_whh_lo; base = b - 14848; }
    else if (b < 27648) { src = Wmu;  hi = g_wmuh;   lo = g_wmul;   base = b - 27136; }
    else                { src = Wsig; hi = g_wsgh;   lo = g_wsgl;   base = b - 27648; }
    size_t i = ((size_t)base * 256 + threadIdx.x) * 4;
    float4 w = *(const float4*)(src + i);
    float f[4] = {w.x, w.y, w.z, w.w};
#pragma unroll
    for (int k = 0; k < 4; k++) {
        bf16 h = __float2bfloat16(f[k]);
        hi[i + k] = h;
        lo[i + k] = __float2bfloat16(f[k] - __bfloat162float(h));
    }
}

// =============================================================================
// gemm_tc (proven; ncu: tensor pipe 67%): C = act(A @ W^T + bias), 3-term split.
// =============================================================================
#define GT_TILE  10240        // 128 rows x 80 B
#define GT_STAGE (4*GT_TILE)
#define GT_SMEM  (2*GT_STAGE)

template <int ACT, int SPLIT>
__global__ __launch_bounds__(256) void gemm_tc(
    const bf16* __restrict__ Ah, const bf16* __restrict__ Al, int lda,
    const bf16* __restrict__ Wh, const bf16* __restrict__ Wl, int ldw,
    const float* __restrict__ bias,
    float* __restrict__ C, int ldc,
    bf16* __restrict__ Ch, bf16* __restrict__ Cl,
    int K)
{
    extern __shared__ __align__(16) char smem[];
    const uint32_t sb = smem_u32(smem);
    const int tid = threadIdx.x;
    const int w = tid >> 5, l = tid & 31;
    const int wm = w >> 1, wn = w & 1;
    const long m0 = (long)blockIdx.y * 128;
    const long n0 = (long)blockIdx.x * 128;

    auto load_stage = [&](int slot, int kt) {
        const uint32_t dst = sb + slot * GT_STAGE;
        const int k0 = kt * 32;
#pragma unroll
        for (int i = 0; i < 2; i++) {
            int o = i * 256 + tid;
            int row = o >> 2, c = o & 3;
            size_t ao = (m0 + row) * (size_t)lda + k0 + c * 8;
            size_t wo = (n0 + row) * (size_t)ldw + k0 + c * 8;
            uint32_t d = dst + row * 80 + c * 16;
            cp16(d,               Ah + ao);
            cp16(d + GT_TILE,     Al + ao);
            cp16(d + 2*GT_TILE,   Wh + wo);
            cp16(d + 3*GT_TILE,   Wl + wo);
        }
        CPC();
    };

    const int nst = K >> 5;
    load_stage(0, 0);
    load_stage(1, 1);

    const uint32_t aoff = (uint32_t)((l & 15) * 80 + (l >> 4) * 16);
    const uint32_t woff = (uint32_t)(((l & 7) + ((l >> 4) & 1) * 8) * 80
                                     + ((l >> 3) & 1) * 16);

    float acc[2][8][4];
#pragma unroll
    for (int a = 0; a < 2; a++)
#pragma unroll
        for (int b = 0; b < 8; b++)
#pragma unroll
            for (int c = 0; c < 4; c++) acc[a][b][c] = 0.0f;

    for (int s = 0; s < nst; s++) {
        const int slot = s & 1;
        if (s + 1 < nst) CPW(1);
        else             CPW(0);
        __syncthreads();

        const uint32_t stg = sb + slot * GT_STAGE;
        const uint32_t aH = stg + wm * 2560 + aoff;
        const uint32_t wH = stg + 2*GT_TILE + wn * 5120 + woff;

#pragma unroll
        for (int k16 = 0; k16 < 2; k16++) {
            uint32_t ah[2][4], al[2][4], wh[4][4], wl[4][4];
#pragma unroll
            for (int mf = 0; mf < 2; mf++) {
                ldm4(aH + mf * 1280 + k16 * 32, ah[mf]);
                ldm4(aH + GT_TILE + mf * 1280 + k16 * 32, al[mf]);
            }
#pragma unroll
            for (int g = 0; g < 4; g++) {
                ldm4(wH + g * 1280 + k16 * 32, wh[g]);
                ldm4(wH + GT_TILE + g * 1280 + k16 * 32, wl[g]);
            }
#pragma unroll
            for (int mf = 0; mf < 2; mf++)
#pragma unroll
                for (int nf = 0; nf < 8; nf++) {
                    const uint32_t* bp = wh[nf >> 1];
                    const uint32_t* lp = wl[nf >> 1];
                    uint32_t b0 = bp[(nf & 1) * 2], b1 = bp[(nf & 1) * 2 + 1];
                    uint32_t c0 = lp[(nf & 1) * 2], c1 = lp[(nf & 1) * 2 + 1];
                    mma16816(acc[mf][nf], ah[mf], b0, b1);
                    mma16816(acc[mf][nf], ah[mf], c0, c1);
                    mma16816(acc[mf][nf], al[mf], b0, b1);
                }
        }
        __syncthreads();
        if (s + 2 < nst) load_stage(slot, s + 2);
    }

    const int r0 = wm * 32 + (l >> 2);
    const int c0 = wn * 64 + (l & 3) * 2;
#pragma unroll
    for (int mf = 0; mf < 2; mf++)
#pragma unroll
        for (int nf = 0; nf < 8; nf++) {
            const long col = n0 + c0 + nf * 8;
            const float b0 = bias[col], b1 = bias[col + 1];
#pragma unroll
            for (int rr = 0; rr < 2; rr++) {
                const long row = m0 + r0 + mf * 16 + rr * 8;
                float v0 = acc[mf][nf][rr * 2]     + b0;
                float v1 = acc[mf][nf][rr * 2 + 1] + b1;
                if (ACT == 1) { v0 = act_elu(v0); v1 = act_elu(v1); }
                else if (ACT == 2) { v0 = act_softplus01(v0); v1 = act_softplus01(v1); }
                if (SPLIT) {
                    bf16 h0 = __float2bfloat16(v0);
                    bf16 h1 = __float2bfloat16(v1);
                    *(__nv_bfloat162*)&Ch[row * (long)ldc + col] =
                        __nv_bfloat162(h0, h1);
                    *(__nv_bfloat162*)&Cl[row * (long)ldc + col] = __nv_bfloat162(
                        __float2bfloat16(v0 - __bfloat162float(h0)),
                        __float2bfloat16(v1 - __bfloat162float(h1)));
                } else {
                    *(float2*)&C[row * (long)ldc + col] = make_float2(v0, v1);
                }
            }
        }
}

// =============================================================================
// step_persist (round-10 proven version, 256 threads): ALL 256 GRU timesteps.
// grid (48 gate-j blocks, 3 k-splits) = 144 CTAs. 4-deep cp.async pipeline.
// Stage slot layout: [A_hi 10240][A_lo 10240][B_hi 5120][B_lo 5120] = 30720
// =============================================================================
#define ST_ALO  10240
#define ST_BHI  20480
#define ST_BLO  25600
#define ST_SZ   30720
#define SM_P    (4 * ST_SZ)      // 122880

__global__ __launch_bounds__(256, 1) void step_persist(
    const bf16* __restrict__ whh_hi,
    const bf16* __restrict__ whh_lo,
    const bf16* __restrict__ hh0,
    const bf16* __restrict__ hl0,
    const float* __restrict__ gx,       // [T][64][6144]
    const float* __restrict__ bhh,
    float* __restrict__ ghp,            // [KSPLIT][64][6144]
    float* __restrict__ hidden,         // [T][64][2048]
    bf16* __restrict__ hhA,
    bf16* __restrict__ hlA,
    unsigned int* __restrict__ cnt)     // [2*T]
{
    extern __shared__ __align__(16) char smem[];
    const uint32_t sb = smem_u32(smem);
    const int tid = threadIdx.x;
    const int w = tid >> 5, l = tid & 31;
    const int jg0 = blockIdx.x * 128;
    const int ks = blockIdx.y;
    const int kbeg = ks * 672;
    const int nst  = (ks == 2) ? 22 : 21;       // 672,672,704
    const int wm = w >> 1, wn = w & 1;
    const int cta = blockIdx.y * 48 + blockIdx.x;

    auto loadA = [&](int s) {
        const uint32_t dst = sb + (s & 3) * ST_SZ;
        const int k0 = kbeg + s * 32;
#pragma unroll
        for (int i = 0; i < 2; i++) {
            int o = i * 256 + tid;
            int row = o >> 2, c = o & 3;
            size_t off = (size_t)(jg0 + row) * CH_ + k0 + c * 8;
            cp16(dst + row * 80 + c * 16,          whh_hi + off);
            cp16(dst + ST_ALO + row * 80 + c * 16, whh_lo + off);
        }
    };
    auto loadB = [&](int s, const bf16* hh_in, const bf16* hl_in) {
        const uint32_t dst = sb + (s & 3) * ST_SZ;
        const int k0 = kbeg + s * 32;
        {
            int o = tid;
            int row = o >> 2, c = o & 3;
            size_t off = (size_t)row * CH_ + k0 + c * 8;
            cp16(dst + ST_BHI + row * 80 + c * 16, hh_in + off);
            cp16(dst + ST_BLO + row * 80 + c * 16, hl_in + off);
        }
    };

#pragma unroll
    for (int i = 0; i < 4; i++) { loadA(i); CPC(); }
#pragma unroll
    for (int i = 0; i < 4; i++) { loadB(i, hh0, hl0); CPC(); }

    const uint32_t aoff = (uint32_t)((l & 15) * 80 + (l >> 4) * 16);
    const uint32_t boff = (uint32_t)(((wn * 32) + (l & 7) + ((l >> 4) & 1) * 8) * 80
                                     + ((l >> 3) & 1) * 16);

    const int idx4 = cta * 256 + tid;
    const bool p2 = (idx4 < B_ * CH_ / 4);
    const int pb  = idx4 >> 9;
    const int pj4 = idx4 & 511;
    float4 br4 = make_float4(0,0,0,0), bz4 = br4, bn4 = br4;
    if (p2) {
        br4 = *(const float4*)(bhh + pj4 * 4);
        bz4 = *(const float4*)(bhh + CH_ + pj4 * 4);
        bn4 = *(const float4*)(bhh + 2 * CH_ + pj4 * 4);
    }
    float4 hp = make_float4(0.f, 0.f, 0.f, 0.f);

    float acc[2][4][4];
#pragma unroll
    for (int a = 0; a < 2; a++)
#pragma unroll
        for (int b = 0; b < 4; b++)
#pragma unroll
            for (int c = 0; c < 4; c++) acc[a][b][c] = 0.0f;

    for (int t = 0; t < T_; t++) {
        const bf16* hh_cur = (t == 0) ? hh0 : hhA + (size_t)(t - 1) * HB_;
        const bf16* hl_cur = (t == 0) ? hl0 : hlA + (size_t)(t - 1) * HB_;

        // ---------------- phase 1: HMMA over this CTA's K chunk ----------------
        for (int s = 0; s < nst; s++) {
            {
                int pend = nst - 1 - s;
                if (pend >= 3)      CPW(3);
                else if (pend == 2) CPW(2);
                else if (pend == 1) CPW(1);
                else                CPW(0);
            }
            __syncthreads();

            const uint32_t stg = sb + (s & 3) * ST_SZ;
            const uint32_t aH  = stg + (uint32_t)(wm * 2560) + aoff;
            const uint32_t bH  = stg + ST_BHI + boff;
            const uint32_t bL  = stg + ST_BLO + boff;

            uint32_t ah[2][2][4], al[2][2][4], bh[2][2][4], bl[2][2][4];
#pragma unroll
            for (int k16 = 0; k16 < 2; k16++) {
#pragma unroll
                for (int mf = 0; mf < 2; mf++) {
                    ldm4(aH + mf * 1280 + k16 * 32, ah[k16][mf]);
                    ldm4(aH + ST_ALO + mf * 1280 + k16 * 32, al[k16][mf]);
                }
#pragma unroll
                for (int nf = 0; nf < 2; nf++) {
                    ldm4(bH + nf * 1280 + k16 * 32, bh[k16][nf]);
                    ldm4(bL + nf * 1280 + k16 * 32, bl[k16][nf]);
                }
            }
            __syncthreads();
            if (s + 4 < nst) { loadA(s + 4); loadB(s + 4, hh_cur, hl_cur); CPC(); }

#pragma unroll
            for (int k16 = 0; k16 < 2; k16++)
#pragma unroll
                for (int mf = 0; mf < 2; mf++)
#pragma unroll
                    for (int nf = 0; nf < 4; nf++) {
                        const uint32_t* bp = bh[k16][nf >> 1];
                        const uint32_t* lp = bl[k16][nf >> 1];
                        uint32_t b0 = bp[(nf & 1) * 2], b1 = bp[(nf & 1) * 2 + 1];
                        uint32_t c0 = lp[(nf & 1) * 2], c1 = lp[(nf & 1) * 2 + 1];
                        mma16816(acc[mf][nf], ah[k16][mf], b0, b1);
                        mma16816(acc[mf][nf], ah[k16][mf], c0, c1);
                        mma16816(acc[mf][nf], al[k16][mf], b0, b1);
                    }
        }

        // write partials + reset acc
        {
            float* base = ghp + (size_t)ks * B_ * G_;
            const int jb = jg0 + wm * 32 + (l >> 2);
            const int bb = wn * 32 + (l & 3) * 2;
#pragma unroll
            for (int mf = 0; mf < 2; mf++)
#pragma unroll
                for (int nf = 0; nf < 4; nf++) {
                    const int j = jb + mf * 16;
                    const int b = bb + nf * 8;
                    base[(size_t)b * G_ + j]           = acc[mf][nf][0];
                    base[(size_t)(b + 1) * G_ + j]     = acc[mf][nf][1];
                    base[(size_t)b * G_ + j + 8]       = acc[mf][nf][2];
                    base[(size_t)(b + 1) * G_ + j + 8] = acc[mf][nf][3];
                    acc[mf][nf][0] = acc[mf][nf][1] = 0.0f;
                    acc[mf][nf][2] = acc[mf][nf][3] = 0.0f;
                }
        }

        // ---- barrier 1; prefetch next-step A during spin ----
        __threadfence();
        __syncthreads();
        if (t + 1 < T_) {
#pragma unroll
            for (int i = 0; i < 4; i++) { loadA(i); CPC(); }
        }
        if (tid == 0) {
            unsigned v = atomicAdd(&cnt[2 * t], 1u) + 1;
            if (v < (unsigned)NCTA_STEP) {
                volatile unsigned* p = &cnt[2 * t];
                while (*p < (unsigned)NCTA_STEP) { }
            }
        }
        __syncthreads();

        // ---------------- phase 2: reduce 3 partials + gates ----------------
        if (p2) {
            const float* gx_t = gx + (size_t)t * B_ * G_;
            const long go = (long)pb * G_ + pj4 * 4;

            float4 xr = *(const float4*)(gx_t + go);
            float4 xz = *(const float4*)(gx_t + go + CH_);
            float4 xn = *(const float4*)(gx_t + go + 2*CH_);

            float4 hr = *(const float4*)(ghp + go);
            float4 hz = *(const float4*)(ghp + go + CH_);
            float4 hn = *(const float4*)(ghp + go + 2*CH_);
#pragma unroll
            for (int s = 1; s < KSPLIT; s++) {
                const float* p = ghp + (size_t)s * B_ * G_ + go;
                float4 a = *(const float4*)(p);
                float4 c = *(const float4*)(p + CH_);
                float4 d = *(const float4*)(p + 2*CH_);
                hr.x += a.x; hr.y += a.y; hr.z += a.z; hr.w += a.w;
                hz.x += c.x; hz.y += c.y; hz.z += c.z; hz.w += c.w;
                hn.x += d.x; hn.y += d.y; hn.z += d.z; hn.w += d.w;
            }
            float xrv[4] = {xr.x, xr.y, xr.z, xr.w};
            float xzv[4] = {xz.x, xz.y, xz.z, xz.w};
            float xnv[4] = {xn.x, xn.y, xn.z, xn.w};
            float hrv[4] = {hr.x + br4.x, hr.y + br4.y, hr.z + br4.z, hr.w + br4.w};
            float hzv[4] = {hz.x + bz4.x, hz.y + bz4.y, hz.z + bz4.z, hz.w + bz4.w};
            float hnv[4] = {hn.x + bn4.x, hn.y + bn4.y, hn.z + bn4.z, hn.w + bn4.w};
            float hpv[4] = {hp.x, hp.y, hp.z, hp.w};
            float ov[4];
#pragma unroll
            for (int i = 0; i < 4; i++) {
                float r = 1.0f / (1.0f + expf(-(xrv[i] + hrv[i])));
                float z = 1.0f / (1.0f + expf(-(xzv[i] + hzv[i])));
                float n = tanhf(xnv[i] + r * hnv[i]);
                ov[i] = (1.0f - z) * n + z * hpv[i];
            }
            hp = make_float4(ov[0], ov[1], ov[2], ov[3]);

            const long ho = (long)pb * CH_ + pj4 * 4;
            *(float4*)(hidden + (size_t)t * HB_ + ho) = hp;
            bf16* hhp = hhA + (size_t)t * HB_ + ho;
            bf16* hlp = hlA + (size_t)t * HB_ + ho;
#pragma unroll
            for (int i = 0; i < 4; i++) {
                bf16 hi = __float2bfloat16(ov[i]);
                hhp[i] = hi;
                hlp[i] = __float2bfloat16(ov[i] - __bfloat162float(hi));
            }
        }

        // ---- barrier 2 (h(t) visible) ----
        __threadfence();
        __syncthreads();
        if (tid == 0) {
            unsigned v = atomicAdd(&cnt[2 * t + 1], 1u) + 1;
            if (v < (unsigned)NCTA_STEP) {
                volatile unsigned* p = &cnt[2 * t + 1];
                while (*p < (unsigned)NCTA_STEP) { }
            }
        }
        __syncthreads();

        // load next-step B stages 0..3 (h(t) just produced)
        if (t + 1 < T_) {
            const bf16* nh = hhA + (size_t)t * HB_;
            const bf16* nl = hlA + (size_t)t * HB_;
#pragma unroll
            for (int i = 0; i < 4; i++) { loadB(i, nh, nl); CPC(); }
        }
    }
}

// =============================================================================
extern "C" void kernel_launch(void* const* d_in, const int* in_sizes, int n_in,
                              void* d_out, int out_size)
{
    const float* x    = (const float*)d_in[0];
    const float* We   = (const float*)d_in[1];
    const float* be   = (const float*)d_in[2];
    const float* Wih  = (const float*)d_in[3];
    const float* bih  = (const float*)d_in[4];
    const float* Whh  = (const float*)d_in[5];
    const float* bhh  = (const float*)d_in[6];
    const float* Wmu  = (const float*)d_in[7];
    const float* bmu  = (const float*)d_in[8];
    const float* Wsig = (const float*)d_in[9];
    const float* bsig = (const float*)d_in[10];

    float* out        = (float*)d_out;
    float* out_mu     = out;
    float* out_sig    = out + (size_t)MB_ * DOUT_;
    float* out_hidden = out + (size_t)2 * MB_ * DOUT_;

    float *p_gx, *p_ghp;
    bf16 *p_xh, *p_xl, *p_xeh, *p_xel, *p_weh, *p_wel, *p_wihh, *p_wihl;
    bf16 *p_whhh, *p_whhl, *p_wmuh, *p_wmul, *p_wsgh, *p_wsgl;
    bf16 *p_hhA, *p_hlA, *p_hh0, *p_hl0;
    unsigned int* p_cnt;
    cudaGetSymbolAddress((void**)&p_gx, g_gx);
    cudaGetSymbolAddress((void**)&p_ghp, g_ghp);
    cudaGetSymbolAddress((void**)&p_xh, g_xh);
    cudaGetSymbolAddress((void**)&p_xl, g_xl);
    cudaGetSymbolAddress((void**)&p_xeh, g_xeh);
    cudaGetSymbolAddress((void**)&p_xel, g_xel);
    cudaGetSymbolAddress((void**)&p_weh, g_weh);
    cudaGetSymbolAddress((void**)&p_wel, g_wel);
    cudaGetSymbolAddress((void**)&p_wihh, g_wihh);
    cudaGetSymbolAddress((void**)&p_wihl, g_wihl);
    cudaGetSymbolAddress((void**)&p_whhh, g_whh_hi);
    cudaGetSymbolAddress((void**)&p_whhl, g_whh_lo);
    cudaGetSymbolAddress((void**)&p_wmuh, g_wmuh);
    cudaGetSymbolAddress((void**)&p_wmul, g_wmul);
    cudaGetSymbolAddress((void**)&p_wsgh, g_wsgh);
    cudaGetSymbolAddress((void**)&p_wsgl, g_wsgl);
    cudaGetSymbolAddress((void**)&p_hhA, g_hhA);
    cudaGetSymbolAddress((void**)&p_hlA, g_hlA);
    cudaGetSymbolAddress((void**)&p_hh0, g_hh0);
    cudaGetSymbolAddress((void**)&p_hl0, g_hl0);
    cudaGetSymbolAddress((void**)&p_cnt, g_cnt);

    cudaFuncSetAttribute(step_persist, cudaFuncAttributeMaxDynamicSharedMemorySize, SM_P);
    cudaFuncSetAttribute(gemm_tc<0,0>, cudaFuncAttributeMaxDynamicSharedMemorySize, GT_SMEM);
    cudaFuncSetAttribute(gemm_tc<1,0>, cudaFuncAttributeMaxDynamicSharedMemorySize, GT_SMEM);
    cudaFuncSetAttribute(gemm_tc<2,0>, cudaFuncAttributeMaxDynamicSharedMemorySize, GT_SMEM);
    cudaFuncSetAttribute(gemm_tc<1,1>, cudaFuncAttributeMaxDynamicSharedMemorySize, GT_SMEM);

    dim3 blk(256);
    // launch order arranged so ncu (-s 5 -c 1) profiles step_persist (launch #6)
    init_kernel<<<512, blk>>>();                                       // 1
    split_all<<<28160, blk>>>(x, We, Wih, Whh, Wmu, Wsig);             // 2
    gemm_tc<1,1><<<dim3(H_/128, MB_/128), blk, GT_SMEM>>>(             // 3: enc
        p_xh, p_xl, DIN_, p_weh, p_wel, DIN_, be,
        nullptr, H_, p_xeh, p_xel, DIN_);
    gemm_tc<0,0><<<dim3(G_/128, MB_/128), blk, GT_SMEM>>>(             // 4: gx
        p_xeh, p_xel, H_, p_wihh, p_wihl, H_, bih,
        p_gx, G_, nullptr, nullptr, H_);
    pad_kernel<<<1, 32>>>();                                           // 5
    step_persist<<<dim3(48, KSPLIT), blk, SM_P>>>(                     // 6
        p_whhh, p_whhl, p_hh0, p_hl0, p_gx, bhh, p_ghp,
        out_hidden, p_hhA, p_hlA, p_cnt);
    gemm_tc<1,0><<<dim3(DOUT_/128, MB_/128), blk, GT_SMEM>>>(          // 7: mu
        p_hhA, p_hlA, CH_, p_wmuh, p_wmul, H_, bmu,
        out_mu, DOUT_, nullptr, nullptr, H_);
    gemm_tc<2,0><<<dim3(DOUT_/128, MB_/128), blk, GT_SMEM>>>(          // 8: sig
        p_hhA + H_, p_hlA + H_, CH_, p_wsgh, p_wsgl, H_, bsig,
        out_sig, DOUT_, nullptr, nullptr, H_);
}

// round 16
// speedup vs baseline: 1.1487x; 1.0150x over previous
#include <cuda_runtime.h>
#include <cuda_bf16.h>
#include <cstdint>
#include <cstddef>

#define T_    256
#define B_    64
#define DIN_  512
#define H_    1024
#define CH_   2048
#define G_    6144
#define DOUT_ 512
#define MB_   (T_*B_)
#define KSPLIT 3
#define NCTA_STEP 144
#define HB_   ((size_t)B_ * CH_)

typedef __nv_bfloat16 bf16;

// ---------------- scratch (device globals) ----------------------------------
__device__ float g_gx[(size_t)MB_ * G_];
__device__ float g_ghp[(size_t)KSPLIT * B_ * G_];
__device__ bf16 g_xh[(size_t)MB_ * DIN_],  g_xl[(size_t)MB_ * DIN_];
__device__ bf16 g_xeh[(size_t)MB_ * H_],   g_xel[(size_t)MB_ * H_];
__device__ bf16 g_weh[(size_t)H_ * DIN_],  g_wel[(size_t)H_ * DIN_];
__device__ bf16 g_wihh[(size_t)G_ * H_],   g_wihl[(size_t)G_ * H_];
__device__ bf16 g_whh_hi[(size_t)G_ * CH_], g_whh_lo[(size_t)G_ * CH_];
__device__ bf16 g_wmuh[(size_t)DOUT_ * H_], g_wmul[(size_t)DOUT_ * H_];
__device__ bf16 g_wsgh[(size_t)DOUT_ * H_], g_wsgl[(size_t)DOUT_ * H_];
__device__ bf16 g_hhA[(size_t)MB_ * CH_],  g_hlA[(size_t)MB_ * CH_];
__device__ bf16 g_hh0[HB_],                g_hl0[HB_];
__device__ unsigned int g_cnt[2 * T_];

__device__ __forceinline__ float act_elu(float v) {
    return v > 0.0f ? v : expm1f(v);
}
__device__ __forceinline__ float act_softplus01(float v) {
    return fmaxf(v, 0.0f) + log1pf(expf(-fabsf(v))) + 0.1f;
}

// ---------------- sm_80-era primitives ---------------------------------------
__device__ __forceinline__ uint32_t smem_u32(const void* p) {
    uint32_t a;
    asm("{ .reg .u64 t; cvta.to.shared.u64 t, %1; cvt.u32.u64 %0, t; }"
        : "=r"(a) : "l"(p));
    return a;
}
__device__ __forceinline__ void cp16(uint32_t dst, const void* src) {
    asm volatile("cp.async.cg.shared.global [%0], [%1], 16;"
                 :: "r"(dst), "l"(src) : "memory");
}
__device__ __forceinline__ void ldm4(uint32_t addr, uint32_t r[4]) {
    asm volatile("ldmatrix.sync.aligned.m8n8.x4.shared.b16 {%0,%1,%2,%3}, [%4];"
                 : "=r"(r[0]), "=r"(r[1]), "=r"(r[2]), "=r"(r[3]) : "r"(addr));
}
__device__ __forceinline__ void mma16816(float d[4], const uint32_t a[4],
                                         uint32_t b0, uint32_t b1) {
    asm volatile(
        "mma.sync.aligned.m16n8k16.row.col.f32.bf16.bf16.f32 "
        "{%0,%1,%2,%3}, {%4,%5,%6,%7}, {%8,%9}, {%0,%1,%2,%3};"
        : "+f"(d[0]), "+f"(d[1]), "+f"(d[2]), "+f"(d[3])
        : "r"(a[0]), "r"(a[1]), "r"(a[2]), "r"(a[3]), "r"(b0), "r"(b1));
}
#define CPW(n) asm volatile("cp.async.wait_group " #n ";" ::: "memory")
#define CPC()  asm volatile("cp.async.commit_group;" ::: "memory")

// =============================================================================
__global__ void init_kernel() {
    int idx = blockIdx.x * 256 + threadIdx.x;          // grid 512 -> 131072
    g_hh0[idx] = __float2bfloat16(0.0f);
    g_hl0[idx] = __float2bfloat16(0.0f);
    if (idx < 2 * T_) g_cnt[idx] = 0u;
}

__global__ void pad_kernel() {}

// one kernel splitting all six fp32 tensors -> bf16 hi/lo (1024 floats/block)
__global__ void split_all(const float* __restrict__ x,
                          const float* __restrict__ We,
                          const float* __restrict__ Wih,
                          const float* __restrict__ Whh,
                          const float* __restrict__ Wmu,
                          const float* __restrict__ Wsig) {
    int b = blockIdx.x;
    const float* src; bf16 *hi, *lo; int base;
    if      (b < 8192)  { src = x;    hi = g_xh;     lo = g_xl;     base = b; }
    else if (b < 8704)  { src = We;   hi = g_weh;    lo = g_wel;    base = b - 8192; }
    else if (b < 14848) { src = Wih;  hi = g_wihh;   lo = g_wihl;   base = b - 8704; }
    else if (b < 27136) { src = Whh;  hi = g_whh_hi; lo = g_whh_lo; base = b - 14848; }
    else if (b < 27648) { src = Wmu;  hi = g_wmuh;   lo = g_wmul;   base = b - 27136; }
    else                { src = Wsig; hi = g_wsgh;   lo = g_wsgl;   base = b - 27648; }
    size_t i = ((size_t)base * 256 + threadIdx.x) * 4;
    float4 w = *(const float4*)(src + i);
    float f[4] = {w.x, w.y, w.z, w.w};
#pragma unroll
    for (int k = 0; k < 4; k++) {
        bf16 h = __float2bfloat16(f[k]);
        hi[i + k] = h;
        lo[i + k] = __float2bfloat16(f[k] - __bfloat162float(h));
    }
}

// =============================================================================
// gemm_tc (proven; tensor pipe 67%): C = act(A @ W^T + bias), 3-term split.
// =============================================================================
#define GT_TILE  10240        // 128 rows x 80 B
#define GT_STAGE (4*GT_TILE)
#define GT_SMEM  (2*GT_STAGE)

template <int ACT, int SPLIT>
__global__ __launch_bounds__(256) void gemm_tc(
    const bf16* __restrict__ Ah, const bf16* __restrict__ Al, int lda,
    const bf16* __restrict__ Wh, const bf16* __restrict__ Wl, int ldw,
    const float* __restrict__ bias,
    float* __restrict__ C, int ldc,
    bf16* __restrict__ Ch, bf16* __restrict__ Cl,
    int K)
{
    extern __shared__ __align__(16) char smem[];
    const uint32_t sb = smem_u32(smem);
    const int tid = threadIdx.x;
    const int w = tid >> 5, l = tid & 31;
    const int wm = w >> 1, wn = w & 1;
    const long m0 = (long)blockIdx.y * 128;
    const long n0 = (long)blockIdx.x * 128;

    auto load_stage = [&](int slot, int kt) {
        const uint32_t dst = sb + slot * GT_STAGE;
        const int k0 = kt * 32;
#pragma unroll
        for (int i = 0; i < 2; i++) {
            int o = i * 256 + tid;
            int row = o >> 2, c = o & 3;
            size_t ao = (m0 + row) * (size_t)lda + k0 + c * 8;
            size_t wo = (n0 + row) * (size_t)ldw + k0 + c * 8;
            uint32_t d = dst + row * 80 + c * 16;
            cp16(d,               Ah + ao);
            cp16(d + GT_TILE,     Al + ao);
            cp16(d + 2*GT_TILE,   Wh + wo);
            cp16(d + 3*GT_TILE,   Wl + wo);
        }
        CPC();
    };

    const int nst = K >> 5;
    load_stage(0, 0);
    load_stage(1, 1);

    const uint32_t aoff = (uint32_t)((l & 15) * 80 + (l >> 4) * 16);
    const uint32_t woff = (uint32_t)(((l & 7) + ((l >> 4) & 1) * 8) * 80
                                     + ((l >> 3) & 1) * 16);

    float acc[2][8][4];
#pragma unroll
    for (int a = 0; a < 2; a++)
#pragma unroll
        for (int b = 0; b < 8; b++)
#pragma unroll
            for (int c = 0; c < 4; c++) acc[a][b][c] = 0.0f;

    for (int s = 0; s < nst; s++) {
        const int slot = s & 1;
        if (s + 1 < nst) CPW(1);
        else             CPW(0);
        __syncthreads();

        const uint32_t stg = sb + slot * GT_STAGE;
        const uint32_t aH = stg + wm * 2560 + aoff;
        const uint32_t wH = stg + 2*GT_TILE + wn * 5120 + woff;

#pragma unroll
        for (int k16 = 0; k16 < 2; k16++) {
            uint32_t ah[2][4], al[2][4], wh[4][4], wl[4][4];
#pragma unroll
            for (int mf = 0; mf < 2; mf++) {
                ldm4(aH + mf * 1280 + k16 * 32, ah[mf]);
                ldm4(aH + GT_TILE + mf * 1280 + k16 * 32, al[mf]);
            }
#pragma unroll
            for (int g = 0; g < 4; g++) {
                ldm4(wH + g * 1280 + k16 * 32, wh[g]);
                ldm4(wH + GT_TILE + g * 1280 + k16 * 32, wl[g]);
            }
#pragma unroll
            for (int mf = 0; mf < 2; mf++)
#pragma unroll
                for (int nf = 0; nf < 8; nf++) {
                    const uint32_t* bp = wh[nf >> 1];
                    const uint32_t* lp = wl[nf >> 1];
                    uint32_t b0 = bp[(nf & 1) * 2], b1 = bp[(nf & 1) * 2 + 1];
                    uint32_t c0 = lp[(nf & 1) * 2], c1 = lp[(nf & 1) * 2 + 1];
                    mma16816(acc[mf][nf], ah[mf], b0, b1);
                    mma16816(acc[mf][nf], ah[mf], c0, c1);
                    mma16816(acc[mf][nf], al[mf], b0, b1);
                }
        }
        __syncthreads();
        if (s + 2 < nst) load_stage(slot, s + 2);
    }

    const int r0 = wm * 32 + (l >> 2);
    const int c0 = wn * 64 + (l & 3) * 2;
#pragma unroll
    for (int mf = 0; mf < 2; mf++)
#pragma unroll
        for (int nf = 0; nf < 8; nf++) {
            const long col = n0 + c0 + nf * 8;
            const float b0 = bias[col], b1 = bias[col + 1];
#pragma unroll
            for (int rr = 0; rr < 2; rr++) {
                const long row = m0 + r0 + mf * 16 + rr * 8;
                float v0 = acc[mf][nf][rr * 2]     + b0;
                float v1 = acc[mf][nf][rr * 2 + 1] + b1;
                if (ACT == 1) { v0 = act_elu(v0); v1 = act_elu(v1); }
                else if (ACT == 2) { v0 = act_softplus01(v0); v1 = act_softplus01(v1); }
                if (SPLIT) {
                    bf16 h0 = __float2bfloat16(v0);
                    bf16 h1 = __float2bfloat16(v1);
                    *(__nv_bfloat162*)&Ch[row * (long)ldc + col] =
                        __nv_bfloat162(h0, h1);
                    *(__nv_bfloat162*)&Cl[row * (long)ldc + col] = __nv_bfloat162(
                        __float2bfloat16(v0 - __bfloat162float(h0)),
                        __float2bfloat16(v1 - __bfloat162float(h1)));
                } else {
                    *(float2*)&C[row * (long)ldc + col] = make_float2(v0, v1);
                }
            }
        }
}

// =============================================================================
// step_persist v4b: BK=64 stages (11/11/10 per k-split), FIXED A warp base
// (wm*4608 = 32 rows x 144 B). grid (48,3) = 144 CTAs, 256 thr, 4-slot pipe.
// Stage slot: [A_hi 18432][A_lo 18432][B_hi 9216][B_lo 9216] = 55296 x 4.
// =============================================================================
#define SP_ALO  18432
#define SP_BHI  36864
#define SP_BLO  46080
#define SP_SZ   55296
#define SM_P    (4 * SP_SZ)      // 221184

__global__ __launch_bounds__(256, 1) void step_persist(
    const bf16* __restrict__ whh_hi,
    const bf16* __restrict__ whh_lo,
    const bf16* __restrict__ hh0,
    const bf16* __restrict__ hl0,
    const float* __restrict__ gx,       // [T][64][6144]
    const float* __restrict__ bhh,
    float* __restrict__ ghp,            // [KSPLIT][64][6144]
    float* __restrict__ hidden,         // [T][64][2048]
    bf16* __restrict__ hhA,
    bf16* __restrict__ hlA,
    unsigned int* __restrict__ cnt)     // [2*T]
{
    extern __shared__ __align__(16) char smem[];
    const uint32_t sb = smem_u32(smem);
    const int tid = threadIdx.x;
    const int w = tid >> 5, l = tid & 31;
    const int jg0 = blockIdx.x * 128;
    const int ks = blockIdx.y;
    const int kbeg = ks * 704;                  // 704,704,640
    const int nst  = (ks == 2) ? 10 : 11;
    const int wm = w >> 1, wn = w & 1;
    const int cta = blockIdx.y * 48 + blockIdx.x;

    auto loadA = [&](int s) {                   // stage s -> slot s&3, 64 k
        const uint32_t dst = sb + (s & 3) * SP_SZ;
        const int k0 = kbeg + s * 64;
#pragma unroll
        for (int i = 0; i < 4; i++) {
            int o = i * 256 + tid;
            int row = o >> 3, c = o & 7;
            size_t off = (size_t)(jg0 + row) * CH_ + k0 + c * 8;
            cp16(dst + row * 144 + c * 16,          whh_hi + off);
            cp16(dst + SP_ALO + row * 144 + c * 16, whh_lo + off);
        }
    };
    auto loadB = [&](int s, const bf16* hh_in, const bf16* hl_in) {
        const uint32_t dst = sb + (s & 3) * SP_SZ;
        const int k0 = kbeg + s * 64;
#pragma unroll
        for (int i = 0; i < 2; i++) {
            int o = i * 256 + tid;
            int row = o >> 3, c = o & 7;
            size_t off = (size_t)row * CH_ + k0 + c * 8;
            cp16(dst + SP_BHI + row * 144 + c * 16, hh_in + off);
            cp16(dst + SP_BLO + row * 144 + c * 16, hl_in + off);
        }
    };

    // prologue: A0..A3 (4 groups), B0..B3 (4 groups)
#pragma unroll
    for (int i = 0; i < 4; i++) { loadA(i); CPC(); }
#pragma unroll
    for (int i = 0; i < 4; i++) { loadB(i, hh0, hl0); CPC(); }

    const uint32_t aoff = (uint32_t)((l & 15) * 144 + (l >> 4) * 16);
    const uint32_t boff = (uint32_t)(((wn * 32) + (l & 7) + ((l >> 4) & 1) * 8) * 144
                                     + ((l >> 3) & 1) * 16);

    const int idx4 = cta * 256 + tid;
    const bool p2 = (idx4 < B_ * CH_ / 4);
    const int pb  = idx4 >> 9;
    const int pj4 = idx4 & 511;
    float4 br4 = make_float4(0,0,0,0), bz4 = br4, bn4 = br4;
    if (p2) {
        br4 = *(const float4*)(bhh + pj4 * 4);
        bz4 = *(const float4*)(bhh + CH_ + pj4 * 4);
        bn4 = *(const float4*)(bhh + 2 * CH_ + pj4 * 4);
    }
    float4 hp = make_float4(0.f, 0.f, 0.f, 0.f);

    float acc[2][4][4];
#pragma unroll
    for (int a = 0; a < 2; a++)
#pragma unroll
        for (int b = 0; b < 4; b++)
#pragma unroll
            for (int c = 0; c < 4; c++) acc[a][b][c] = 0.0f;

    for (int t = 0; t < T_; t++) {
        const bf16* hh_cur = (t == 0) ? hh0 : hhA + (size_t)(t - 1) * HB_;
        const bf16* hl_cur = (t == 0) ? hl0 : hlA + (size_t)(t - 1) * HB_;

        // ---------------- phase 1: HMMA, BK=64 stages ----------------
        for (int s = 0; s < nst; s++) {
            {
                int pend = nst - 1 - s;
                if (pend >= 3)      CPW(3);
                else if (pend == 2) CPW(2);
                else if (pend == 1) CPW(1);
                else                CPW(0);
            }
            __syncthreads();

            const uint32_t stg = sb + (s & 3) * SP_SZ;
            const uint32_t aH  = stg + (uint32_t)(wm * 4608) + aoff;   // 32 rows*144
            const uint32_t bH  = stg + SP_BHI + boff;
            const uint32_t bL  = stg + SP_BLO + boff;

#pragma unroll
            for (int k16 = 0; k16 < 4; k16++) {
                uint32_t ah[2][4], al[2][4], bh[2][4], bl[2][4];
#pragma unroll
                for (int mf = 0; mf < 2; mf++) {
                    ldm4(aH + mf * 2304 + k16 * 32, ah[mf]);        // 16 rows apart
                    ldm4(aH + SP_ALO + mf * 2304 + k16 * 32, al[mf]);
                }
#pragma unroll
                for (int nf = 0; nf < 2; nf++) {
                    ldm4(bH + nf * 2304 + k16 * 32, bh[nf]);
                    ldm4(bL + nf * 2304 + k16 * 32, bl[nf]);
                }
#pragma unroll
                for (int mf = 0; mf < 2; mf++)
#pragma unroll
                    for (int nf = 0; nf < 4; nf++) {
                        const uint32_t* bp = bh[nf >> 1];
                        const uint32_t* lp = bl[nf >> 1];
                        uint32_t b0 = bp[(nf & 1) * 2], b1 = bp[(nf & 1) * 2 + 1];
                        uint32_t c0 = lp[(nf & 1) * 2], c1 = lp[(nf & 1) * 2 + 1];
                        mma16816(acc[mf][nf], ah[mf], b0, b1);
                        mma16816(acc[mf][nf], ah[mf], c0, c1);
                        mma16816(acc[mf][nf], al[mf], b0, b1);
                    }
            }
            __syncthreads();
            if (s + 4 < nst) { loadA(s + 4); loadB(s + 4, hh_cur, hl_cur); CPC(); }
        }

        // write partials + reset acc
        {
            float* base = ghp + (size_t)ks * B_ * G_;
            const int jb = jg0 + wm * 32 + (l >> 2);
            const int bb = wn * 32 + (l & 3) * 2;
#pragma unroll
            for (int mf = 0; mf < 2; mf++)
#pragma unroll
                for (int nf = 0; nf < 4; nf++) {
                    const int j = jb + mf * 16;
                    const int b = bb + nf * 8;
                    base[(size_t)b * G_ + j]           = acc[mf][nf][0];
                    base[(size_t)(b + 1) * G_ + j]     = acc[mf][nf][1];
                    base[(size_t)b * G_ + j + 8]       = acc[mf][nf][2];
                    base[(size_t)(b + 1) * G_ + j + 8] = acc[mf][nf][3];
                    acc[mf][nf][0] = acc[mf][nf][1] = 0.0f;
                    acc[mf][nf][2] = acc[mf][nf][3] = 0.0f;
                }
        }

        // prefetch gx_t into registers (independent of barriers)
        float4 xr, xz, xn;
        if (p2) {
            const float* gx_t = gx + (size_t)t * B_ * G_;
            const long go = (long)pb * G_ + pj4 * 4;
            xr = *(const float4*)(gx_t + go);
            xz = *(const float4*)(gx_t + go + CH_);
            xn = *(const float4*)(gx_t + go + 2*CH_);
        }

        // ---- barrier 1; prefetch next-step A during spin ----
        __threadfence();
        __syncthreads();
        if (t + 1 < T_) {
#pragma unroll
            for (int i = 0; i < 4; i++) { loadA(i); CPC(); }
        }
        if (tid == 0) {
            unsigned v = atomicAdd(&cnt[2 * t], 1u) + 1;
            if (v < (unsigned)NCTA_STEP) {
                volatile unsigned* p = &cnt[2 * t];
                while (*p < (unsigned)NCTA_STEP) { }
            }
        }
        __syncthreads();

        // ---------------- phase 2: reduce 3 partials + gates ----------------
        if (p2) {
            const long go = (long)pb * G_ + pj4 * 4;

            float4 hr = *(const float4*)(ghp + go);
            float4 hz = *(const float4*)(ghp + go + CH_);
            float4 hn = *(const float4*)(ghp + go + 2*CH_);
#pragma unroll
            for (int s = 1; s < KSPLIT; s++) {
                const float* p = ghp + (size_t)s * B_ * G_ + go;
                float4 a = *(const float4*)(p);
                float4 c = *(const float4*)(p + CH_);
                float4 d = *(const float4*)(p + 2*CH_);
                hr.x += a.x; hr.y += a.y; hr.z += a.z; hr.w += a.w;
                hz.x += c.x; hz.y += c.y; hz.z += c.z; hz.w += c.w;
                hn.x += d.x; hn.y += d.y; hn.z += d.z; hn.w += d.w;
            }
            float xrv[4] = {xr.x, xr.y, xr.z, xr.w};
            float xzv[4] = {xz.x, xz.y, xz.z, xz.w};
            float xnv[4] = {xn.x, xn.y, xn.z, xn.w};
            float hrv[4] = {hr.x + br4.x, hr.y + br4.y, hr.z + br4.z, hr.w + br4.w};
            float hzv[4] = {hz.x + bz4.x, hz.y + bz4.y, hz.z + bz4.z, hz.w + bz4.w};
            float hnv[4] = {hn.x + bn4.x, hn.y + bn4.y, hn.z + bn4.z, hn.w + bn4.w};
            float hpv[4] = {hp.x, hp.y, hp.z, hp.w};
            float ov[4];
#pragma unroll
            for (int i = 0; i < 4; i++) {
                float r = 1.0f / (1.0f + expf(-(xrv[i] + hrv[i])));
                float z = 1.0f / (1.0f + expf(-(xzv[i] + hzv[i])));
                float n = tanhf(xnv[i] + r * hnv[i]);
                ov[i] = (1.0f - z) * n + z * hpv[i];
            }
            hp = make_float4(ov[0], ov[1], ov[2], ov[3]);

            const long ho = (long)pb * CH_ + pj4 * 4;
            *(float4*)(hidden + (size_t)t * HB_ + ho) = hp;
            bf16* hhp = hhA + (size_t)t * HB_ + ho;
            bf16* hlp = hlA + (size_t)t * HB_ + ho;
#pragma unroll
            for (int i = 0; i < 4; i++) {
                bf16 hi = __float2bfloat16(ov[i]);
                hhp[i] = hi;
                hlp[i] = __float2bfloat16(ov[i] - __bfloat162float(hi));
            }
        }

        // ---- barrier 2 (h(t) visible) ----
        __threadfence();
        __syncthreads();
        if (tid == 0) {
            unsigned v = atomicAdd(&cnt[2 * t + 1], 1u) + 1;
            if (v < (unsigned)NCTA_STEP) {
                volatile unsigned* p = &cnt[2 * t + 1];
                while (*p < (unsigned)NCTA_STEP) { }
            }
        }
        __syncthreads();

        // load next-step B stages 0..3 (h(t) just produced)
        if (t + 1 < T_) {
            const bf16* nh = hhA + (size_t)t * HB_;
            const bf16* nl = hlA + (size_t)t * HB_;
#pragma unroll
            for (int i = 0; i < 4; i++) { loadB(i, nh, nl); CPC(); }
        }
    }
}

// =============================================================================
extern "C" void kernel_launch(void* const* d_in, const int* in_sizes, int n_in,
                              void* d_out, int out_size)
{
    const float* x    = (const float*)d_in[0];
    const float* We   = (const float*)d_in[1];
    const float* be   = (const float*)d_in[2];
    const float* Wih  = (const float*)d_in[3];
    const float* bih  = (const float*)d_in[4];
    const float* Whh  = (const float*)d_in[5];
    const float* bhh  = (const float*)d_in[6];
    const float* Wmu  = (const float*)d_in[7];
    const float* bmu  = (const float*)d_in[8];
    const float* Wsig = (const float*)d_in[9];
    const float* bsig = (const float*)d_in[10];

    float* out        = (float*)d_out;
    float* out_mu     = out;
    float* out_sig    = out + (size_t)MB_ * DOUT_;
    float* out_hidden = out + (size_t)2 * MB_ * DOUT_;

    float *p_gx, *p_ghp;
    bf16 *p_xh, *p_xl, *p_xeh, *p_xel, *p_weh, *p_wel, *p_wihh, *p_wihl;
    bf16 *p_whhh, *p_whhl, *p_wmuh, *p_wmul, *p_wsgh, *p_wsgl;
    bf16 *p_hhA, *p_hlA, *p_hh0, *p_hl0;
    unsigned int* p_cnt;
    cudaGetSymbolAddress((void**)&p_gx, g_gx);
    cudaGetSymbolAddress((void**)&p_ghp, g_ghp);
    cudaGetSymbolAddress((void**)&p_xh, g_xh);
    cudaGetSymbolAddress((void**)&p_xl, g_xl);
    cudaGetSymbolAddress((void**)&p_xeh, g_xeh);
    cudaGetSymbolAddress((void**)&p_xel, g_xel);
    cudaGetSymbolAddress((void**)&p_weh, g_weh);
    cudaGetSymbolAddress((void**)&p_wel, g_wel);
    cudaGetSymbolAddress((void**)&p_wihh, g_wihh);
    cudaGetSymbolAddress((void**)&p_wihl, g_wihl);
    cudaGetSymbolAddress((void**)&p_whhh, g_whh_hi);
    cudaGetSymbolAddress((void**)&p_whhl, g_whh_lo);
    cudaGetSymbolAddress((void**)&p_wmuh, g_wmuh);
    cudaGetSymbolAddress((void**)&p_wmul, g_wmul);
    cudaGetSymbolAddress((void**)&p_wsgh, g_wsgh);
    cudaGetSymbolAddress((void**)&p_wsgl, g_wsgl);
    cudaGetSymbolAddress((void**)&p_hhA, g_hhA);
    cudaGetSymbolAddress((void**)&p_hlA, g_hlA);
    cudaGetSymbolAddress((void**)&p_hh0, g_hh0);
    cudaGetSymbolAddress((void**)&p_hl0, g_hl0);
    cudaGetSymbolAddress((void**)&p_cnt, g_cnt);

    cudaFuncSetAttribute(step_persist, cudaFuncAttributeMaxDynamicSharedMemorySize, SM_P);
    cudaFuncSetAttribute(gemm_tc<0,0>, cudaFuncAttributeMaxDynamicSharedMemorySize, GT_SMEM);
    cudaFuncSetAttribute(gemm_tc<1,0>, cudaFuncAttributeMaxDynamicSharedMemorySize, GT_SMEM);
    cudaFuncSetAttribute(gemm_tc<2,0>, cudaFuncAttributeMaxDynamicSharedMemorySize, GT_SMEM);
    cudaFuncSetAttribute(gemm_tc<1,1>, cudaFuncAttributeMaxDynamicSharedMemorySize, GT_SMEM);

    dim3 blk(256);
    init_kernel<<<512, blk>>>();                                       // 1
    split_all<<<28160, blk>>>(x, We, Wih, Whh, Wmu, Wsig);             // 2
    gemm_tc<1,1><<<dim3(H_/128, MB_/128), blk, GT_SMEM>>>(             // 3: enc
        p_xh, p_xl, DIN_, p_weh, p_wel, DIN_, be,
        nullptr, H_, p_xeh, p_xel, DIN_);
    gemm_tc<0,0><<<dim3(G_/128, MB_/128), blk, GT_SMEM>>>(             // 4: gx
        p_xeh, p_xel, H_, p_wihh, p_wihl, H_, bih,
        p_gx, G_, nullptr, nullptr, H_);
    pad_kernel<<<1, 32>>>();                                           // 5
    step_persist<<<dim3(48, KSPLIT), blk, SM_P>>>(                     // 6
        p_whhh, p_whhl, p_hh0, p_hl0, p_gx, bhh, p_ghp,
        out_hidden, p_hhA, p_hlA, p_cnt);
    gemm_tc<1,0><<<dim3(DOUT_/128, MB_/128), blk, GT_SMEM>>>(          // 7: mu
        p_hhA, p_hlA, CH_, p_wmuh, p_wmul, H_, bmu,
        out_mu, DOUT_, nullptr, nullptr, H_);
    gemm_tc<2,0><<<dim3(DOUT_/128, MB_/128), blk, GT_SMEM>>>(          // 8: sig
        p_hhA + H_, p_hlA + H_, CH_, p_wsgh, p_wsgl, H_, bsig,
        out_sig, DOUT_, nullptr, nullptr, H_);
}

// round 17
// speedup vs baseline: 1.1492x; 1.0004x over previous
#include <cuda_runtime.h>
#include <cuda_bf16.h>
#include <cstdint>
#include <cstddef>

#define T_    256
#define B_    64
#define DIN_  512
#define H_    1024
#define CH_   2048
#define G_    6144
#define DOUT_ 512
#define MB_   (T_*B_)
#define KSPLIT 3
#define NCTA_STEP 144
#define HB_   ((size_t)B_ * CH_)

typedef __nv_bfloat16 bf16;

// ---------------- scratch (device globals) ----------------------------------
__device__ float g_gx[(size_t)MB_ * G_];
__device__ float g_ghp[(size_t)KSPLIT * B_ * G_];
__device__ bf16 g_xh[(size_t)MB_ * DIN_],  g_xl[(size_t)MB_ * DIN_];
__device__ bf16 g_xeh[(size_t)MB_ * H_],   g_xel[(size_t)MB_ * H_];
__device__ bf16 g_weh[(size_t)H_ * DIN_],  g_wel[(size_t)H_ * DIN_];
__device__ bf16 g_wihh[(size_t)G_ * H_],   g_wihl[(size_t)G_ * H_];
__device__ bf16 g_whh_hi[(size_t)G_ * CH_], g_whh_lo[(size_t)G_ * CH_];
__device__ bf16 g_wmuh[(size_t)DOUT_ * H_], g_wmul[(size_t)DOUT_ * H_];
__device__ bf16 g_wsgh[(size_t)DOUT_ * H_], g_wsgl[(size_t)DOUT_ * H_];
__device__ bf16 g_hhA[(size_t)MB_ * CH_],  g_hlA[(size_t)MB_ * CH_];
__device__ bf16 g_hh0[HB_],                g_hl0[HB_];
__device__ unsigned int g_cnt[2 * T_];

__device__ __forceinline__ float act_elu(float v) {
    return v > 0.0f ? v : expm1f(v);
}
__device__ __forceinline__ float act_softplus01(float v) {
    return fmaxf(v, 0.0f) + log1pf(expf(-fabsf(v))) + 0.1f;
}

// ---------------- sm_80-era primitives ---------------------------------------
__device__ __forceinline__ uint32_t smem_u32(const void* p) {
    uint32_t a;
    asm("{ .reg .u64 t; cvta.to.shared.u64 t, %1; cvt.u32.u64 %0, t; }"
        : "=r"(a) : "l"(p));
    return a;
}
__device__ __forceinline__ void cp16(uint32_t dst, const void* src) {
    asm volatile("cp.async.cg.shared.global [%0], [%1], 16;"
                 :: "r"(dst), "l"(src) : "memory");
}
__device__ __forceinline__ void ldm4(uint32_t addr, uint32_t r[4]) {
    asm volatile("ldmatrix.sync.aligned.m8n8.x4.shared.b16 {%0,%1,%2,%3}, [%4];"
                 : "=r"(r[0]), "=r"(r[1]), "=r"(r[2]), "=r"(r[3]) : "r"(addr));
}
__device__ __forceinline__ void mma16816(float d[4], const uint32_t a[4],
                                         uint32_t b0, uint32_t b1) {
    asm volatile(
        "mma.sync.aligned.m16n8k16.row.col.f32.bf16.bf16.f32 "
        "{%0,%1,%2,%3}, {%4,%5,%6,%7}, {%8,%9}, {%0,%1,%2,%3};"
        : "+f"(d[0]), "+f"(d[1]), "+f"(d[2]), "+f"(d[3])
        : "r"(a[0]), "r"(a[1]), "r"(a[2]), "r"(a[3]), "r"(b0), "r"(b1));
}
#define CPW(n) asm volatile("cp.async.wait_group " #n ";" ::: "memory")
#define CPC()  asm volatile("cp.async.commit_group;" ::: "memory")

// =============================================================================
__global__ void init_kernel() {
    int idx = blockIdx.x * 256 + threadIdx.x;          // grid 512 -> 131072
    g_hh0[idx] = __float2bfloat16(0.0f);
    g_hl0[idx] = __float2bfloat16(0.0f);
    if (idx < 2 * T_) g_cnt[idx] = 0u;
}

__global__ void pad_kernel() {}

// one kernel splitting all six fp32 tensors -> bf16 hi/lo (1024 floats/block)
__global__ void split_all(const float* __restrict__ x,
                          const float* __restrict__ We,
                          const float* __restrict__ Wih,
                          const float* __restrict__ Whh,
                          const float* __restrict__ Wmu,
                          const float* __restrict__ Wsig) {
    int b = blockIdx.x;
    const float* src; bf16 *hi, *lo; int base;
    if      (b < 8192)  { src = x;    hi = g_xh;     lo = g_xl;     base = b; }
    else if (b < 8704)  { src = We;   hi = g_weh;    lo = g_wel;    base = b - 8192; }
    else if (b < 14848) { src = Wih;  hi = g_wihh;   lo = g_wihl;   base = b - 8704; }
    else if (b < 27136) { src = Whh;  hi = g_whh_hi; lo = g_whh_lo; base = b - 14848; }
    else if (b < 27648) { src = Wmu;  hi = g_wmuh;   lo = g_wmul;   base = b - 27136; }
    else                { src = Wsig; hi = g_wsgh;   lo = g_wsgl;   base = b - 27648; }
    size_t i = ((size_t)base * 256 + threadIdx.x) * 4;
    float4 w = *(const float4*)(src + i);
    float f[4] = {w.x, w.y, w.z, w.w};
#pragma unroll
    for (int k = 0; k < 4; k++) {
        bf16 h = __float2bfloat16(f[k]);
        hi[i + k] = h;
        lo[i + k] = __float2bfloat16(f[k] - __bfloat162float(h));
    }
}

// =============================================================================
// gemm_tc (proven; tensor pipe 67%): C = act(A @ W^T + bias), 3-term split.
// =============================================================================
#define GT_TILE  10240        // 128 rows x 80 B
#define GT_STAGE (4*GT_TILE)
#define GT_SMEM  (2*GT_STAGE)

template <int ACT, int SPLIT>
__global__ __launch_bounds__(256) void gemm_tc(
    const bf16* __restrict__ Ah, const bf16* __restrict__ Al, int lda,
    const bf16* __restrict__ Wh, const bf16* __restrict__ Wl, int ldw,
    const float* __restrict__ bias,
    float* __restrict__ C, int ldc,
    bf16* __restrict__ Ch, bf16* __restrict__ Cl,
    int K)
{
    extern __shared__ __align__(16) char smem[];
    const uint32_t sb = smem_u32(smem);
    const int tid = threadIdx.x;
    const int w = tid >> 5, l = tid & 31;
    const int wm = w >> 1, wn = w & 1;
    const long m0 = (long)blockIdx.y * 128;
    const long n0 = (long)blockIdx.x * 128;

    auto load_stage = [&](int slot, int kt) {
        const uint32_t dst = sb + slot * GT_STAGE;
        const int k0 = kt * 32;
#pragma unroll
        for (int i = 0; i < 2; i++) {
            int o = i * 256 + tid;
            int row = o >> 2, c = o & 3;
            size_t ao = (m0 + row) * (size_t)lda + k0 + c * 8;
            size_t wo = (n0 + row) * (size_t)ldw + k0 + c * 8;
            uint32_t d = dst + row * 80 + c * 16;
            cp16(d,               Ah + ao);
            cp16(d + GT_TILE,     Al + ao);
            cp16(d + 2*GT_TILE,   Wh + wo);
            cp16(d + 3*GT_TILE,   Wl + wo);
        }
        CPC();
    };

    const int nst = K >> 5;
    load_stage(0, 0);
    load_stage(1, 1);

    const uint32_t aoff = (uint32_t)((l & 15) * 80 + (l >> 4) * 16);
    const uint32_t woff = (uint32_t)(((l & 7) + ((l >> 4) & 1) * 8) * 80
                                     + ((l >> 3) & 1) * 16);

    float acc[2][8][4];
#pragma unroll
    for (int a = 0; a < 2; a++)
#pragma unroll
        for (int b = 0; b < 8; b++)
#pragma unroll
            for (int c = 0; c < 4; c++) acc[a][b][c] = 0.0f;

    for (int s = 0; s < nst; s++) {
        const int slot = s & 1;
        if (s + 1 < nst) CPW(1);
        else             CPW(0);
        __syncthreads();

        const uint32_t stg = sb + slot * GT_STAGE;
        const uint32_t aH = stg + wm * 2560 + aoff;
        const uint32_t wH = stg + 2*GT_TILE + wn * 5120 + woff;

#pragma unroll
        for (int k16 = 0; k16 < 2; k16++) {
            uint32_t ah[2][4], al[2][4], wh[4][4], wl[4][4];
#pragma unroll
            for (int mf = 0; mf < 2; mf++) {
                ldm4(aH + mf * 1280 + k16 * 32, ah[mf]);
                ldm4(aH + GT_TILE + mf * 1280 + k16 * 32, al[mf]);
            }
#pragma unroll
            for (int g = 0; g < 4; g++) {
                ldm4(wH + g * 1280 + k16 * 32, wh[g]);
                ldm4(wH + GT_TILE + g * 1280 + k16 * 32, wl[g]);
            }
#pragma unroll
            for (int mf = 0; mf < 2; mf++)
#pragma unroll
                for (int nf = 0; nf < 8; nf++) {
                    const uint32_t* bp = wh[nf >> 1];
                    const uint32_t* lp = wl[nf >> 1];
                    uint32_t b0 = bp[(nf & 1) * 2], b1 = bp[(nf & 1) * 2 + 1];
                    uint32_t c0 = lp[(nf & 1) * 2], c1 = lp[(nf & 1) * 2 + 1];
                    mma16816(acc[mf][nf], ah[mf], b0, b1);
                    mma16816(acc[mf][nf], ah[mf], c0, c1);
                    mma16816(acc[mf][nf], al[mf], b0, b1);
                }
        }
        __syncthreads();
        if (s + 2 < nst) load_stage(slot, s + 2);
    }

    const int r0 = wm * 32 + (l >> 2);
    const int c0 = wn * 64 + (l & 3) * 2;
#pragma unroll
    for (int mf = 0; mf < 2; mf++)
#pragma unroll
        for (int nf = 0; nf < 8; nf++) {
            const long col = n0 + c0 + nf * 8;
            const float b0 = bias[col], b1 = bias[col + 1];
#pragma unroll
            for (int rr = 0; rr < 2; rr++) {
                const long row = m0 + r0 + mf * 16 + rr * 8;
                float v0 = acc[mf][nf][rr * 2]     + b0;
                float v1 = acc[mf][nf][rr * 2 + 1] + b1;
                if (ACT == 1) { v0 = act_elu(v0); v1 = act_elu(v1); }
                else if (ACT == 2) { v0 = act_softplus01(v0); v1 = act_softplus01(v1); }
                if (SPLIT) {
                    bf16 h0 = __float2bfloat16(v0);
                    bf16 h1 = __float2bfloat16(v1);
                    *(__nv_bfloat162*)&Ch[row * (long)ldc + col] =
                        __nv_bfloat162(h0, h1);
                    *(__nv_bfloat162*)&Cl[row * (long)ldc + col] = __nv_bfloat162(
                        __float2bfloat16(v0 - __bfloat162float(h0)),
                        __float2bfloat16(v1 - __bfloat162float(h1)));
                } else {
                    *(float2*)&C[row * (long)ldc + col] = make_float2(v0, v1);
                }
            }
        }
}

// =============================================================================
// step_persist v4b: BK=64 stages (11/11/10 per k-split), FIXED A warp base
// (wm*4608 = 32 rows x 144 B). grid (48,3) = 144 CTAs, 256 thr, 4-slot pipe.
// Stage slot: [A_hi 18432][A_lo 18432][B_hi 9216][B_lo 9216] = 55296 x 4.
// =============================================================================
#define SP_ALO  18432
#define SP_BHI  36864
#define SP_BLO  46080
#define SP_SZ   55296
#define SM_P    (4 * SP_SZ)      // 221184

__global__ __launch_bounds__(256, 1) void step_persist(
    const bf16* __restrict__ whh_hi,
    const bf16* __restrict__ whh_lo,
    const bf16* __restrict__ hh0,
    const bf16* __restrict__ hl0,
    const float* __restrict__ gx,       // [T][64][6144]
    const float* __restrict__ bhh,
    float* __restrict__ ghp,            // [KSPLIT][64][6144]
    float* __restrict__ hidden,         // [T][64][2048]
    bf16* __restrict__ hhA,
    bf16* __restrict__ hlA,
    unsigned int* __restrict__ cnt)     // [2*T]
{
    extern __shared__ __align__(16) char smem[];
    const uint32_t sb = smem_u32(smem);
    const int tid = threadIdx.x;
    const int w = tid >> 5, l = tid & 31;
    const int jg0 = blockIdx.x * 128;
    const int ks = blockIdx.y;
    const int kbeg = ks * 704;                  // 704,704,640
    const int nst  = (ks == 2) ? 10 : 11;
    const int wm = w >> 1, wn = w & 1;
    const int cta = blockIdx.y * 48 + blockIdx.x;

    auto loadA = [&](int s) {                   // stage s -> slot s&3, 64 k
        const uint32_t dst = sb + (s & 3) * SP_SZ;
        const int k0 = kbeg + s * 64;
#pragma unroll
        for (int i = 0; i < 4; i++) {
            int o = i * 256 + tid;
            int row = o >> 3, c = o & 7;
            size_t off = (size_t)(jg0 + row) * CH_ + k0 + c * 8;
            cp16(dst + row * 144 + c * 16,          whh_hi + off);
            cp16(dst + SP_ALO + row * 144 + c * 16, whh_lo + off);
        }
    };
    auto loadB = [&](int s, const bf16* hh_in, const bf16* hl_in) {
        const uint32_t dst = sb + (s & 3) * SP_SZ;
        const int k0 = kbeg + s * 64;
#pragma unroll
        for (int i = 0; i < 2; i++) {
            int o = i * 256 + tid;
            int row = o >> 3, c = o & 7;
            size_t off = (size_t)row * CH_ + k0 + c * 8;
            cp16(dst + SP_BHI + row * 144 + c * 16, hh_in + off);
            cp16(dst + SP_BLO + row * 144 + c * 16, hl_in + off);
        }
    };

    // prologue: A0..A3 (4 groups), B0..B3 (4 groups)
#pragma unroll
    for (int i = 0; i < 4; i++) { loadA(i); CPC(); }
#pragma unroll
    for (int i = 0; i < 4; i++) { loadB(i, hh0, hl0); CPC(); }

    const uint32_t aoff = (uint32_t)((l & 15) * 144 + (l >> 4) * 16);
    const uint32_t boff = (uint32_t)(((wn * 32) + (l & 7) + ((l >> 4) & 1) * 8) * 144
                                     + ((l >> 3) & 1) * 16);

    const int idx4 = cta * 256 + tid;
    const bool p2 = (idx4 < B_ * CH_ / 4);
    const int pb  = idx4 >> 9;
    const int pj4 = idx4 & 511;
    float4 br4 = make_float4(0,0,0,0), bz4 = br4, bn4 = br4;
    if (p2) {
        br4 = *(const float4*)(bhh + pj4 * 4);
        bz4 = *(const float4*)(bhh + CH_ + pj4 * 4);
        bn4 = *(const float4*)(bhh + 2 * CH_ + pj4 * 4);
    }
    float4 hp = make_float4(0.f, 0.f, 0.f, 0.f);

    float acc[2][4][4];
#pragma unroll
    for (int a = 0; a < 2; a++)
#pragma unroll
        for (int b = 0; b < 4; b++)
#pragma unroll
            for (int c = 0; c < 4; c++) acc[a][b][c] = 0.0f;

    for (int t = 0; t < T_; t++) {
        const bf16* hh_cur = (t == 0) ? hh0 : hhA + (size_t)(t - 1) * HB_;
        const bf16* hl_cur = (t == 0) ? hl0 : hlA + (size_t)(t - 1) * HB_;

        // ---------------- phase 1: HMMA, BK=64 stages ----------------
        for (int s = 0; s < nst; s++) {
            {
                int pend = nst - 1 - s;
                if (pend >= 3)      CPW(3);
                else if (pend == 2) CPW(2);
                else if (pend == 1) CPW(1);
                else                CPW(0);
            }
            __syncthreads();

            const uint32_t stg = sb + (s & 3) * SP_SZ;
            const uint32_t aH  = stg + (uint32_t)(wm * 4608) + aoff;   // 32 rows*144
            const uint32_t bH  = stg + SP_BHI + boff;
            const uint32_t bL  = stg + SP_BLO + boff;

#pragma unroll
            for (int k16 = 0; k16 < 4; k16++) {
                uint32_t ah[2][4], al[2][4], bh[2][4], bl[2][4];
#pragma unroll
                for (int mf = 0; mf < 2; mf++) {
                    ldm4(aH + mf * 2304 + k16 * 32, ah[mf]);        // 16 rows apart
                    ldm4(aH + SP_ALO + mf * 2304 + k16 * 32, al[mf]);
                }
#pragma unroll
                for (int nf = 0; nf < 2; nf++) {
                    ldm4(bH + nf * 2304 + k16 * 32, bh[nf]);
                    ldm4(bL + nf * 2304 + k16 * 32, bl[nf]);
                }
#pragma unroll
                for (int mf = 0; mf < 2; mf++)
#pragma unroll
                    for (int nf = 0; nf < 4; nf++) {
                        const uint32_t* bp = bh[nf >> 1];
                        const uint32_t* lp = bl[nf >> 1];
                        uint32_t b0 = bp[(nf & 1) * 2], b1 = bp[(nf & 1) * 2 + 1];
                        uint32_t c0 = lp[(nf & 1) * 2], c1 = lp[(nf & 1) * 2 + 1];
                        mma16816(acc[mf][nf], ah[mf], b0, b1);
                        mma16816(acc[mf][nf], ah[mf], c0, c1);
                        mma16816(acc[mf][nf], al[mf], b0, b1);
                    }
            }
            __syncthreads();
            if (s + 4 < nst) { loadA(s + 4); loadB(s + 4, hh_cur, hl_cur); CPC(); }
        }

        // write partials + reset acc
        {
            float* base = ghp + (size_t)ks * B_ * G_;
            const int jb = jg0 + wm * 32 + (l >> 2);
            const int bb = wn * 32 + (l & 3) * 2;
#pragma unroll
            for (int mf = 0; mf < 2; mf++)
#pragma unroll
                for (int nf = 0; nf < 4; nf++) {
                    const int j = jb + mf * 16;
                    const int b = bb + nf * 8;
                    base[(size_t)b * G_ + j]           = acc[mf][nf][0];
                    base[(size_t)(b + 1) * G_ + j]     = acc[mf][nf][1];
                    base[(size_t)b * G_ + j + 8]       = acc[mf][nf][2];
                    base[(size_t)(b + 1) * G_ + j + 8] = acc[mf][nf][3];
                    acc[mf][nf][0] = acc[mf][nf][1] = 0.0f;
                    acc[mf][nf][2] = acc[mf][nf][3] = 0.0f;
                }
        }

        // prefetch gx_t into registers (independent of barriers)
        float4 xr, xz, xn;
        if (p2) {
            const float* gx_t = gx + (size_t)t * B_ * G_;
            const long go = (long)pb * G_ + pj4 * 4;
            xr = *(const float4*)(gx_t + go);
            xz = *(const float4*)(gx_t + go + CH_);
            xn = *(const float4*)(gx_t + go + 2*CH_);
        }

        // ---- barrier 1; prefetch next-step A during spin ----
        __threadfence();
        __syncthreads();
        if (t + 1 < T_) {
#pragma unroll
            for (int i = 0; i < 4; i++) { loadA(i); CPC(); }
        }
        if (tid == 0) {
            unsigned v = atomicAdd(&cnt[2 * t], 1u) + 1;
            if (v < (unsigned)NCTA_STEP) {
                volatile unsigned* p = &cnt[2 * t];
                while (*p < (unsigned)NCTA_STEP) { }
            }
        }
        __syncthreads();

        // ---------------- phase 2: reduce 3 partials + gates ----------------
        if (p2) {
            const long go = (long)pb * G_ + pj4 * 4;

            float4 hr = *(const float4*)(ghp + go);
            float4 hz = *(const float4*)(ghp + go + CH_);
            float4 hn = *(const float4*)(ghp + go + 2*CH_);
#pragma unroll
            for (int s = 1; s < KSPLIT; s++) {
                const float* p = ghp + (size_t)s * B_ * G_ + go;
                float4 a = *(const float4*)(p);
                float4 c = *(const float4*)(p + CH_);
                float4 d = *(const float4*)(p + 2*CH_);
                hr.x += a.x; hr.y += a.y; hr.z += a.z; hr.w += a.w;
                hz.x += c.x; hz.y += c.y; hz.z += c.z; hz.w += c.w;
                hn.x += d.x; hn.y += d.y; hn.z += d.z; hn.w += d.w;
            }
            float xrv[4] = {xr.x, xr.y, xr.z, xr.w};
            float xzv[4] = {xz.x, xz.y, xz.z, xz.w};
            float xnv[4] = {xn.x, xn.y, xn.z, xn.w};
            float hrv[4] = {hr.x + br4.x, hr.y + br4.y, hr.z + br4.z, hr.w + br4.w};
            float hzv[4] = {hz.x + bz4.x, hz.y + bz4.y, hz.z + bz4.z, hz.w + bz4.w};
            float hnv[4] = {hn.x + bn4.x, hn.y + bn4.y, hn.z + bn4.z, hn.w + bn4.w};
            float hpv[4] = {hp.x, hp.y, hp.z, hp.w};
            float ov[4];
#pragma unroll
            for (int i = 0; i < 4; i++) {
                float r = 1.0f / (1.0f + expf(-(xrv[i] + hrv[i])));
                float z = 1.0f / (1.0f + expf(-(xzv[i] + hzv[i])));
                float n = tanhf(xnv[i] + r * hnv[i]);
                ov[i] = (1.0f - z) * n + z * hpv[i];
            }
            hp = make_float4(ov[0], ov[1], ov[2], ov[3]);

            const long ho = (long)pb * CH_ + pj4 * 4;
            *(float4*)(hidden + (size_t)t * HB_ + ho) = hp;
            bf16* hhp = hhA + (size_t)t * HB_ + ho;
            bf16* hlp = hlA + (size_t)t * HB_ + ho;
#pragma unroll
            for (int i = 0; i < 4; i++) {
                bf16 hi = __float2bfloat16(ov[i]);
                hhp[i] = hi;
                hlp[i] = __float2bfloat16(ov[i] - __bfloat162float(hi));
            }
        }

        // ---- barrier 2 (h(t) visible) ----
        __threadfence();
        __syncthreads();
        if (tid == 0) {
            unsigned v = atomicAdd(&cnt[2 * t + 1], 1u) + 1;
            if (v < (unsigned)NCTA_STEP) {
                volatile unsigned* p = &cnt[2 * t + 1];
                while (*p < (unsigned)NCTA_STEP) { }
            }
        }
        __syncthreads();

        // load next-step B stages 0..3 (h(t) just produced)
        if (t + 1 < T_) {
            const bf16* nh = hhA + (size_t)t * HB_;
            const bf16* nl = hlA + (size_t)t * HB_;
#pragma unroll
            for (int i = 0; i < 4; i++) { loadB(i, nh, nl); CPC(); }
        }
    }
}

// =============================================================================
extern "C" void kernel_launch(void* const* d_in, const int* in_sizes, int n_in,
                              void* d_out, int out_size)
{
    const float* x    = (const float*)d_in[0];
    const float* We   = (const float*)d_in[1];
    const float* be   = (const float*)d_in[2];
    const float* Wih  = (const float*)d_in[3];
    const float* bih  = (const float*)d_in[4];
    const float* Whh  = (const float*)d_in[5];
    const float* bhh  = (const float*)d_in[6];
    const float* Wmu  = (const float*)d_in[7];
    const float* bmu  = (const float*)d_in[8];
    const float* Wsig = (const float*)d_in[9];
    const float* bsig = (const float*)d_in[10];

    float* out        = (float*)d_out;
    float* out_mu     = out;
    float* out_sig    = out + (size_t)MB_ * DOUT_;
    float* out_hidden = out + (size_t)2 * MB_ * DOUT_;

    float *p_gx, *p_ghp;
    bf16 *p_xh, *p_xl, *p_xeh, *p_xel, *p_weh, *p_wel, *p_wihh, *p_wihl;
    bf16 *p_whhh, *p_whhl, *p_wmuh, *p_wmul, *p_wsgh, *p_wsgl;
    bf16 *p_hhA, *p_hlA, *p_hh0, *p_hl0;
    unsigned int* p_cnt;
    cudaGetSymbolAddress((void**)&p_gx, g_gx);
    cudaGetSymbolAddress((void**)&p_ghp, g_ghp);
    cudaGetSymbolAddress((void**)&p_xh, g_xh);
    cudaGetSymbolAddress((void**)&p_xl, g_xl);
    cudaGetSymbolAddress((void**)&p_xeh, g_xeh);
    cudaGetSymbolAddress((void**)&p_xel, g_xel);
    cudaGetSymbolAddress((void**)&p_weh, g_weh);
    cudaGetSymbolAddress((void**)&p_wel, g_wel);
    cudaGetSymbolAddress((void**)&p_wihh, g_wihh);
    cudaGetSymbolAddress((void**)&p_wihl, g_wihl);
    cudaGetSymbolAddress((void**)&p_whhh, g_whh_hi);
    cudaGetSymbolAddress((void**)&p_whhl, g_whh_lo);
    cudaGetSymbolAddress((void**)&p_wmuh, g_wmuh);
    cudaGetSymbolAddress((void**)&p_wmul, g_wmul);
    cudaGetSymbolAddress((void**)&p_wsgh, g_wsgh);
    cudaGetSymbolAddress((void**)&p_wsgl, g_wsgl);
    cudaGetSymbolAddress((void**)&p_hhA, g_hhA);
    cudaGetSymbolAddress((void**)&p_hlA, g_hlA);
    cudaGetSymbolAddress((void**)&p_hh0, g_hh0);
    cudaGetSymbolAddress((void**)&p_hl0, g_hl0);
    cudaGetSymbolAddress((void**)&p_cnt, g_cnt);

    cudaFuncSetAttribute(step_persist, cudaFuncAttributeMaxDynamicSharedMemorySize, SM_P);
    cudaFuncSetAttribute(gemm_tc<0,0>, cudaFuncAttributeMaxDynamicSharedMemorySize, GT_SMEM);
    cudaFuncSetAttribute(gemm_tc<1,0>, cudaFuncAttributeMaxDynamicSharedMemorySize, GT_SMEM);
    cudaFuncSetAttribute(gemm_tc<2,0>, cudaFuncAttributeMaxDynamicSharedMemorySize, GT_SMEM);
    cudaFuncSetAttribute(gemm_tc<1,1>, cudaFuncAttributeMaxDynamicSharedMemorySize, GT_SMEM);

    dim3 blk(256);
    init_kernel<<<512, blk>>>();                                       // 1
    split_all<<<28160, blk>>>(x, We, Wih, Whh, Wmu, Wsig);             // 2
    gemm_tc<1,1><<<dim3(H_/128, MB_/128), blk, GT_SMEM>>>(             // 3: enc
        p_xh, p_xl, DIN_, p_weh, p_wel, DIN_, be,
        nullptr, H_, p_xeh, p_xel, DIN_);
    gemm_tc<0,0><<<dim3(G_/128, MB_/128), blk, GT_SMEM>>>(             // 4: gx
        p_xeh, p_xel, H_, p_wihh, p_wihl, H_, bih,
        p_gx, G_, nullptr, nullptr, H_);
    pad_kernel<<<1, 32>>>();                                           // 5
    step_persist<<<dim3(48, KSPLIT), blk, SM_P>>>(                     // 6
        p_whhh, p_whhl, p_hh0, p_hl0, p_gx, bhh, p_ghp,
        out_hidden, p_hhA, p_hlA, p_cnt);
    gemm_tc<1,0><<<dim3(DOUT_/128, MB_/128), blk, GT_SMEM>>>(          // 7: mu
        p_hhA, p_hlA, CH_, p_wmuh, p_wmul, H_, bmu,
        out_mu, DOUT_, nullptr, nullptr, H_);
    gemm_tc<2,0><<<dim3(DOUT_/128, MB_/128), blk, GT_SMEM>>>(          // 8: sig
        p_hhA + H_, p_hlA + H_, CH_, p_wsgh, p_wsgl, H_, bsig,
        out_sig, DOUT_, nullptr, nullptr, H_);
}